// round 1
// baseline (speedup 1.0000x reference)
#include <cuda_runtime.h>
#include <mma.h>

using namespace nvcuda;

#define NB 64
#define NP 16
#define NT 256
#define NI 256
#define NH 512
#define NO 5
#define NK (NP*NI)   /* 4096 */

// Scratch (device globals per harness rules; ~138 MB)
__device__ float g_pre[4][NT][NB][NH];   // [gate][t][b][h]  x-side pre-activations (no bias)
__device__ float g_h[2][NB*NH];          // ping-pong hidden state
__device__ float g_c[NB*NH];             // cell state
__device__ float g_Wh[4][NH*NH];         // tf32-rounded recurrent weights

// ---------------------------------------------------------------------------
// One-time per-call: round W_h to tf32 (RN) so mma reads clean tf32 operands.
__global__ __launch_bounds__(256) void convert_wh(const float* __restrict__ w0,
                                                  const float* __restrict__ w1,
                                                  const float* __restrict__ w2,
                                                  const float* __restrict__ w3) {
    int idx = blockIdx.x * blockDim.x + threadIdx.x;
    if (idx < NH * NH) {
        g_Wh[0][idx] = wmma::__float_to_tf32(w0[idx]);
        g_Wh[1][idx] = wmma::__float_to_tf32(w1[idx]);
        g_Wh[2][idx] = wmma::__float_to_tf32(w2[idx]);
        g_Wh[3][idx] = wmma::__float_to_tf32(w3[idx]);
    }
}

__global__ __launch_bounds__(256) void init_state() {
    int idx = blockIdx.x * blockDim.x + threadIdx.x;
    if (idx < NB * NH) { g_h[0][idx] = 0.f; g_c[idx] = 0.f; }
}

// ---------------------------------------------------------------------------
// Pre-activation GEMM with fused embedding gather.
// Per CTA: one (t, gate, 64-col) tile -> output 64(b) x 64(h), K = 4096.
// A[b, k] = emb[x[b, p, t], i] with k = p*256+i, token 0 => zero row.
__global__ __launch_bounds__(256) void pre_kernel(const int*  __restrict__ x,
                                                  const float* __restrict__ emb,
                                                  const float* __restrict__ Wf,
                                                  const float* __restrict__ Wi,
                                                  const float* __restrict__ Wg,
                                                  const float* __restrict__ Wo) {
    const int h0   = blockIdx.x * 64;
    const int t    = blockIdx.y;
    const int gate = blockIdx.z;
    const float* W = (gate == 0) ? Wf : (gate == 1) ? Wi : (gate == 2) ? Wg : Wo;

    __shared__ int   sTok[NP * 64];      // tokens for this t: [p][b]
    __shared__ float sA[64 * 36];        // 64 rows x 32 k (ld 36)
    __shared__ float sB[32 * 68];        // 32 k x 64 h (ld 68)

    const int tid = threadIdx.x;

    #pragma unroll
    for (int e = 0; e < 4; e++) {
        int idx = e * 256 + tid;             // 1024 tokens
        int p = idx >> 6, b = idx & 63;
        sTok[idx] = x[b * (NP * NT) + p * NT + t];
    }
    __syncthreads();

    const int w = tid >> 5;
    const int warpRow = w >> 1;              // 0..3 (16 rows each)
    const int warpCol = w & 1;               // 0..1 (32 cols each)

    wmma::fragment<wmma::accumulator, 16, 16, 8, float> acc[2];
    wmma::fill_fragment(acc[0], 0.f);
    wmma::fill_fragment(acc[1], 0.f);

    for (int k0 = 0; k0 < NK; k0 += 32) {
        const int p  = k0 >> 8;
        const int i0 = k0 & 255;
        #pragma unroll
        for (int e = 0; e < 8; e++) {
            int idx = e * 256 + tid;
            int row = idx >> 5, col = idx & 31;
            int tok = sTok[p * 64 + row];
            float v = tok ? __ldg(emb + (long)tok * NI + i0 + col) : 0.f;
            sA[row * 36 + col] = wmma::__float_to_tf32(v);
        }
        #pragma unroll
        for (int e = 0; e < 8; e++) {
            int idx = e * 256 + tid;
            int row = idx >> 6, col = idx & 63;
            sB[row * 68 + col] = wmma::__float_to_tf32(W[(long)(k0 + row) * NH + h0 + col]);
        }
        __syncthreads();

        #pragma unroll
        for (int kk = 0; kk < 4; kk++) {
            wmma::fragment<wmma::matrix_a, 16, 16, 8, wmma::precision::tf32, wmma::row_major> fa;
            wmma::load_matrix_sync(fa, &sA[(warpRow * 16) * 36 + kk * 8], 36);
            #pragma unroll
            for (int f = 0; f < 2; f++) {
                wmma::fragment<wmma::matrix_b, 16, 16, 8, wmma::precision::tf32, wmma::row_major> fb;
                wmma::load_matrix_sync(fb, &sB[(kk * 8) * 68 + warpCol * 32 + f * 16], 68);
                wmma::mma_sync(acc[f], fa, fb, acc[f]);
            }
        }
        __syncthreads();
    }

    float* outp = &g_pre[gate][t][warpRow * 16][h0 + warpCol * 32];
    wmma::store_matrix_sync(outp,      acc[0], NH, wmma::mem_row_major);
    wmma::store_matrix_sync(outp + 16, acc[1], NH, wmma::mem_row_major);
}

// ---------------------------------------------------------------------------
// One LSTM step, fused: 4 gate h-GEMMs (WMMA tf32) + elementwise c/h update.
// Grid (16 colTiles, 4 rowTiles) = 64 CTAs; each CTA owns 16 batches x 32 cols.
// ping selects h buffers (read g_h[ping], write g_h[ping^1]); c updated in place.
__global__ __launch_bounds__(256) void step_kernel(const float* __restrict__ bf,
                                                   const float* __restrict__ bi,
                                                   const float* __restrict__ bg,
                                                   const float* __restrict__ bo,
                                                   int t, int ping) {
    const float* h_in  = g_h[ping];
    float*       h_out = g_h[ping ^ 1];

    const int colTile = blockIdx.x;          // 0..15
    const int rowTile = blockIdx.y;          // 0..3
    const int row0 = rowTile * 16;
    const int tid  = threadIdx.x;
    const int w    = tid >> 5;
    const int gate = w >> 1;                 // 0..3
    const int half = w & 1;                  // 0..1
    const int col0 = colTile * 32 + half * 16;

    __shared__ float sAcc[4][16][32];

    wmma::fragment<wmma::accumulator, 16, 16, 8, float> acc;
    wmma::fill_fragment(acc, 0.f);
    const float* Wg_ = g_Wh[gate];

    #pragma unroll 4
    for (int k = 0; k < NH; k += 8) {
        wmma::fragment<wmma::matrix_a, 16, 16, 8, wmma::precision::tf32, wmma::row_major> fa;
        wmma::load_matrix_sync(fa, h_in + row0 * NH + k, NH);
        #pragma unroll
        for (int i = 0; i < fa.num_elements; i++) fa.x[i] = wmma::__float_to_tf32(fa.x[i]);
        wmma::fragment<wmma::matrix_b, 16, 16, 8, wmma::precision::tf32, wmma::row_major> fb;
        wmma::load_matrix_sync(fb, Wg_ + k * NH + col0, NH);
        wmma::mma_sync(acc, fa, fb, acc);
    }
    wmma::store_matrix_sync(&sAcc[gate][0][half * 16], acc, 32, wmma::mem_row_major);
    __syncthreads();

    #pragma unroll
    for (int e = 0; e < 2; e++) {
        int idx = e * 256 + tid;             // 512 elements
        int r = idx >> 5, cc = idx & 31;
        int b    = row0 + r;
        int hcol = colTile * 32 + cc;
        float pf = g_pre[0][t][b][hcol] + bf[hcol] + sAcc[0][r][cc];
        float pi = g_pre[1][t][b][hcol] + bi[hcol] + sAcc[1][r][cc];
        float pg = g_pre[2][t][b][hcol] + bg[hcol] + sAcc[2][r][cc];
        float po = g_pre[3][t][b][hcol] + bo[hcol] + sAcc[3][r][cc];
        float f = 1.f / (1.f + expf(-pf));
        float i = 1.f / (1.f + expf(-pi));
        float g = tanhf(pg);
        float o = 1.f / (1.f + expf(-po));
        float cn = f * g_c[b * NH + hcol] + i * g;
        g_c[b * NH + hcol] = cn;
        h_out[b * NH + hcol] = o * tanhf(cn);
    }
}

// ---------------------------------------------------------------------------
// Head: out = h_final @ W_lin + b_lin; also emit h_t and c_t.
// Final h lives in g_h[0] (T=256 even).
__global__ __launch_bounds__(256) void final_kernel(const float* __restrict__ Wl,
                                                    const float* __restrict__ bl,
                                                    float* __restrict__ out,
                                                    int out_size) {
    const float* h = g_h[0];
    if (blockIdx.x == 0) {
        for (int idx = threadIdx.x; idx < NB * NO; idx += blockDim.x) {
            int b = idx / NO, o = idx % NO;
            float s = bl[o];
            #pragma unroll 8
            for (int k = 0; k < NH; k++) s += h[b * NH + k] * Wl[k * NO + o];
            if (idx < out_size) out[idx] = s;
        }
    }
    int gidx   = blockIdx.x * blockDim.x + threadIdx.x;
    int stride = gridDim.x * blockDim.x;
    for (int i = gidx; i < NB * NH; i += stride) {
        if (NB * NO + i < out_size)           out[NB * NO + i] = h[i];
        if (NB * NO + NB * NH + i < out_size) out[NB * NO + NB * NH + i] = g_c[i];
    }
}

// ---------------------------------------------------------------------------
extern "C" void kernel_launch(void* const* d_in, const int* in_sizes, int n_in,
                              void* d_out, int out_size) {
    const int*   x   = (const int*)  d_in[0];
    const float* emb = (const float*)d_in[1];
    const float* Wfx = (const float*)d_in[2];
    const float* Wfh = (const float*)d_in[3];
    const float* bf  = (const float*)d_in[4];
    const float* Wix = (const float*)d_in[5];
    const float* Wih = (const float*)d_in[6];
    const float* bi  = (const float*)d_in[7];
    const float* Wgx = (const float*)d_in[8];
    const float* Wgh = (const float*)d_in[9];
    const float* bg  = (const float*)d_in[10];
    const float* Wox = (const float*)d_in[11];
    const float* Woh = (const float*)d_in[12];
    const float* bo  = (const float*)d_in[13];
    const float* Wl  = (const float*)d_in[14];
    const float* bl  = (const float*)d_in[15];
    float* out = (float*)d_out;

    convert_wh<<<(NH * NH + 255) / 256, 256>>>(Wfh, Wih, Wgh, Woh);
    init_state<<<(NB * NH + 255) / 256, 256>>>();

    dim3 gpre(NH / 64, NT, 4);
    pre_kernel<<<gpre, 256>>>(x, emb, Wfx, Wix, Wgx, Wox);

    for (int t = 0; t < NT; t++) {
        step_kernel<<<dim3(16, 4), 256>>>(bf, bi, bg, bo, t, t & 1);
    }

    final_kernel<<<132, 256>>>(Wl, bl, out, out_size);
}

// round 2
// speedup vs baseline: 2.1536x; 2.1536x over previous
#include <cuda_runtime.h>
#include <mma.h>

using namespace nvcuda;

#define NB 64
#define NP 16
#define NT 256
#define NI 256
#define NH 512
#define NO 5
#define NK (NP*NI)   /* 4096 */

// Scratch (device globals per harness rules)
__device__ float g_pre[4][NT][NB][NH];   // [gate][t][b][h]  x-side pre-activations (no bias)
__device__ float g_h[2][NB*NH];          // ping-pong hidden state
__device__ float g_c[NB*NH];             // cell state
__device__ int   g_count;                // global barrier counter

__global__ __launch_bounds__(256) void init_state() {
    int idx = blockIdx.x * blockDim.x + threadIdx.x;
    if (idx < NB * NH) { g_h[0][idx] = 0.f; }
    if (idx == 0) g_count = 0;
}

// ---------------------------------------------------------------------------
// Pre-activation GEMM with fused embedding gather. 128x128 tiles, K=4096,
// register double-buffered. grid = (16 ntile, 128 mtile), 256 threads.
// Row r of the 16384-row A matrix = (t = r>>6, b = r&63); A[r, k=p*256+i] =
// emb[x[b,p,t], i] (token 0 => zero). N dim = gate*512 + h.
__global__ __launch_bounds__(256) void pre_kernel(const int*  __restrict__ x,
                                                  const float* __restrict__ emb,
                                                  const float* __restrict__ Wf,
                                                  const float* __restrict__ Wi,
                                                  const float* __restrict__ Wg,
                                                  const float* __restrict__ Wo) {
    extern __shared__ char smem_raw[];
    int*   sTok = (int*)smem_raw;                       // [2][16][64]
    float* sA   = (float*)(smem_raw + 8192);            // [2][128][36]
    float* sB   = sA + 2 * 128 * 36;                    // [2][32][132]

    const int gate = blockIdx.x >> 2;
    const int h0   = (blockIdx.x & 3) * 128;
    const int t0   = blockIdx.y * 2;                    // 2 t-values per CTA
    const float* W = (gate == 0) ? Wf : (gate == 1) ? Wi : (gate == 2) ? Wg : Wo;

    const int tid = threadIdx.x;

    // Load the 2048 tokens this CTA needs: [tt][p][b]
    #pragma unroll
    for (int e = 0; e < 8; e++) {
        int idx = e * 256 + tid;
        int tt = idx >> 10, rem = idx & 1023;
        int p = rem >> 6, b = rem & 63;
        sTok[idx] = x[b * (NP * NT) + p * NT + (t0 + tt)];
    }
    __syncthreads();

    const int w      = tid >> 5;
    const int warpM  = w & 3;            // 4 m-tiles of 32 rows
    const int warpN  = w >> 2;           // 2 n-tiles of 64 cols
    const int m0     = warpM * 32;
    const int n0     = warpN * 64;

    wmma::fragment<wmma::accumulator, 16, 16, 8, float> acc[2][4];
    #pragma unroll
    for (int i = 0; i < 2; i++)
        #pragma unroll
        for (int j = 0; j < 4; j++) wmma::fill_fragment(acc[i][j], 0.f);

    float4 ra[4], rb[4];

    // ---- slab loaders (k-slab = 32) ----
    auto loadA = [&](float4* r, int s) {
        const int p  = (s * 32) >> 8;
        const int i0 = (s * 32) & 255;
        #pragma unroll
        for (int e = 0; e < 4; e++) {
            int idx = e * 256 + tid;           // 1024 float4
            int row = idx >> 3, c4 = idx & 7;  // row 0..127, col4 0..7
            int tok = sTok[(row >> 6) * 1024 + p * 64 + (row & 63)];
            if (tok) r[e] = *reinterpret_cast<const float4*>(emb + (long)tok * NI + i0 + c4 * 4);
            else     r[e] = make_float4(0.f, 0.f, 0.f, 0.f);
        }
    };
    auto loadB = [&](float4* r, int s) {
        const int k0 = s * 32;
        #pragma unroll
        for (int e = 0; e < 4; e++) {
            int idx = e * 256 + tid;           // 1024 float4
            int row = idx >> 5, c4 = idx & 31; // row 0..31, col 0..127
            r[e] = *reinterpret_cast<const float4*>(W + (long)(k0 + row) * NH + h0 + c4 * 4);
        }
    };
    auto cvt4 = [](float4 v) {
        v.x = wmma::__float_to_tf32(v.x); v.y = wmma::__float_to_tf32(v.y);
        v.z = wmma::__float_to_tf32(v.z); v.w = wmma::__float_to_tf32(v.w);
        return v;
    };
    auto sts = [&](const float4* a, const float4* b, int buf) {
        float* dA = sA + buf * 128 * 36;
        float* dB = sB + buf * 32 * 132;
        #pragma unroll
        for (int e = 0; e < 4; e++) {
            int idx = e * 256 + tid;
            int row = idx >> 3, c4 = idx & 7;
            float4 v = cvt4(a[e]);
            dA[row * 36 + c4 * 4 + 0] = v.x; dA[row * 36 + c4 * 4 + 1] = v.y;
            dA[row * 36 + c4 * 4 + 2] = v.z; dA[row * 36 + c4 * 4 + 3] = v.w;
        }
        #pragma unroll
        for (int e = 0; e < 4; e++) {
            int idx = e * 256 + tid;
            int row = idx >> 5, c4 = idx & 31;
            float4 v = cvt4(b[e]);
            dB[row * 132 + c4 * 4 + 0] = v.x; dB[row * 132 + c4 * 4 + 1] = v.y;
            dB[row * 132 + c4 * 4 + 2] = v.z; dB[row * 132 + c4 * 4 + 3] = v.w;
        }
    };

    loadA(ra, 0); loadB(rb, 0);
    sts(ra, rb, 0);
    __syncthreads();

    int cur = 0;
    for (int s = 0; s < 128; s++) {
        if (s + 1 < 128) { loadA(ra, s + 1); loadB(rb, s + 1); }

        const float* bA = sA + cur * 128 * 36;
        const float* bB = sB + cur * 32 * 132;
        #pragma unroll
        for (int kk = 0; kk < 4; kk++) {
            wmma::fragment<wmma::matrix_a, 16, 16, 8, wmma::precision::tf32, wmma::row_major> fa[2];
            wmma::load_matrix_sync(fa[0], bA + (m0 +  0) * 36 + kk * 8, 36);
            wmma::load_matrix_sync(fa[1], bA + (m0 + 16) * 36 + kk * 8, 36);
            #pragma unroll
            for (int j = 0; j < 4; j++) {
                wmma::fragment<wmma::matrix_b, 16, 16, 8, wmma::precision::tf32, wmma::row_major> fb;
                wmma::load_matrix_sync(fb, bB + (kk * 8) * 132 + n0 + j * 16, 132);
                wmma::mma_sync(acc[0][j], fa[0], fb, acc[0][j]);
                wmma::mma_sync(acc[1][j], fa[1], fb, acc[1][j]);
            }
        }
        if (s + 1 < 128) {
            sts(ra, rb, cur ^ 1);
            __syncthreads();
            cur ^= 1;
        }
    }

    // Epilogue: store 8 16x16 frags
    #pragma unroll
    for (int ms = 0; ms < 2; ms++) {
        int rbase = m0 + ms * 16;                  // 0..112, within one t block of 64
        int t = t0 + (rbase >> 6);
        int b0 = rbase & 63;
        #pragma unroll
        for (int ns = 0; ns < 4; ns++) {
            float* p = &g_pre[gate][t][b0][h0 + n0 + ns * 16];
            wmma::store_matrix_sync(p, acc[ms][ns], NH, wmma::mem_row_major);
        }
    }
}

// ---------------------------------------------------------------------------
// Persistent recurrence: 64 CTAs x 256 threads, 1 CTA/SM, all co-resident.
// CTA owns 8 h-columns across all 4 gates (N=32). W slice + full h staged in
// smem; c lives in registers; global barrier between steps.
__global__ __launch_bounds__(256) void rec_kernel(const float* __restrict__ Wfh,
                                                  const float* __restrict__ Wih,
                                                  const float* __restrict__ Wgh,
                                                  const float* __restrict__ Woh,
                                                  const float* __restrict__ bfp,
                                                  const float* __restrict__ bip,
                                                  const float* __restrict__ bgp,
                                                  const float* __restrict__ bop) {
    extern __shared__ float sm[];
    float* sW   = sm;                    // [512][40], col = gate*8 + c
    float* sH   = sW + 512 * 40;         // [64][520]
    float* sAcc = sH + 64 * 520;         // [64][36]

    const int cta = blockIdx.x;
    const int tid = threadIdx.x;
    const int colbase = cta * 8;

    // Load this CTA's W slice (one time, tf32-rounded)
    {
        const float* Wp[4] = {Wfh, Wih, Wgh, Woh};
        #pragma unroll 8
        for (int e = 0; e < 64; e++) {
            int idx = e * 256 + tid;          // 16384
            int row = idx >> 5, c = idx & 31;
            float v = Wp[c >> 3][row * NH + colbase + (c & 7)];
            sW[row * 40 + c] = wmma::__float_to_tf32(v);
        }
    }

    // Per-thread elementwise ownership: (b, c0) and (b, c0+1)
    const int b  = tid >> 2;
    const int c0 = (2 * tid) & 7;             // even
    const float bf0 = bfp[colbase + c0], bf1 = bfp[colbase + c0 + 1];
    const float bi0 = bip[colbase + c0], bi1 = bip[colbase + c0 + 1];
    const float bg0 = bgp[colbase + c0], bg1 = bgp[colbase + c0 + 1];
    const float bo0 = bop[colbase + c0], bo1 = bop[colbase + c0 + 1];
    float c_reg0 = 0.f, c_reg1 = 0.f;

    const int w  = tid >> 5;
    const int m0 = (w >> 1) * 16;             // 4 m-tiles
    const int n0 = (w & 1) * 16;              // 2 n-tiles

    __syncthreads();

    for (int t = 0; t < NT; t++) {
        if (t > 0) {
            if (tid == 0) {
                int target = 64 * t;
                while (*(volatile int*)&g_count < target) { }
            }
            __syncthreads();
        }

        // prefetch pre-activations for this thread (independent of h)
        const float2 pf = *reinterpret_cast<const float2*>(&g_pre[0][t][b][colbase + c0]);
        const float2 pi = *reinterpret_cast<const float2*>(&g_pre[1][t][b][colbase + c0]);
        const float2 pg = *reinterpret_cast<const float2*>(&g_pre[2][t][b][colbase + c0]);
        const float2 po = *reinterpret_cast<const float2*>(&g_pre[3][t][b][colbase + c0]);

        // stage h (L2-only loads; L1 may be stale across steps)
        const float* hin = g_h[t & 1];
        #pragma unroll 8
        for (int e = 0; e < 32; e++) {
            int idx = e * 256 + tid;          // 8192 float4
            int row = idx >> 7, c4 = idx & 127;
            float4 v = __ldcg(reinterpret_cast<const float4*>(hin + row * NH + c4 * 4));
            sH[row * 520 + c4 * 4 + 0] = wmma::__float_to_tf32(v.x);
            sH[row * 520 + c4 * 4 + 1] = wmma::__float_to_tf32(v.y);
            sH[row * 520 + c4 * 4 + 2] = wmma::__float_to_tf32(v.z);
            sH[row * 520 + c4 * 4 + 3] = wmma::__float_to_tf32(v.w);
        }
        __syncthreads();

        // GEMM: [64x512] @ [512x32]
        wmma::fragment<wmma::accumulator, 16, 16, 8, float> acc;
        wmma::fill_fragment(acc, 0.f);
        #pragma unroll 4
        for (int k = 0; k < 64; k++) {
            wmma::fragment<wmma::matrix_a, 16, 16, 8, wmma::precision::tf32, wmma::row_major> fa;
            wmma::load_matrix_sync(fa, sH + m0 * 520 + k * 8, 520);
            wmma::fragment<wmma::matrix_b, 16, 16, 8, wmma::precision::tf32, wmma::row_major> fb;
            wmma::load_matrix_sync(fb, sW + (k * 8) * 40 + n0, 40);
            wmma::mma_sync(acc, fa, fb, acc);
        }
        wmma::store_matrix_sync(sAcc + m0 * 36 + n0, acc, 36, wmma::mem_row_major);
        __syncthreads();

        // Elementwise update (2 elements per thread)
        float af0 = sAcc[b * 36 +  0 + c0], af1 = sAcc[b * 36 +  0 + c0 + 1];
        float ai0 = sAcc[b * 36 +  8 + c0], ai1 = sAcc[b * 36 +  8 + c0 + 1];
        float ag0 = sAcc[b * 36 + 16 + c0], ag1 = sAcc[b * 36 + 16 + c0 + 1];
        float ao0 = sAcc[b * 36 + 24 + c0], ao1 = sAcc[b * 36 + 24 + c0 + 1];

        float f0 = 1.f / (1.f + expf(-(pf.x + bf0 + af0)));
        float f1 = 1.f / (1.f + expf(-(pf.y + bf1 + af1)));
        float i0 = 1.f / (1.f + expf(-(pi.x + bi0 + ai0)));
        float i1 = 1.f / (1.f + expf(-(pi.y + bi1 + ai1)));
        float gg0 = tanhf(pg.x + bg0 + ag0);
        float gg1 = tanhf(pg.y + bg1 + ag1);
        float o0 = 1.f / (1.f + expf(-(po.x + bo0 + ao0)));
        float o1 = 1.f / (1.f + expf(-(po.y + bo1 + ao1)));

        c_reg0 = f0 * c_reg0 + i0 * gg0;
        c_reg1 = f1 * c_reg1 + i1 * gg1;
        float h0v = o0 * tanhf(c_reg0);
        float h1v = o1 * tanhf(c_reg1);

        float* hout = g_h[(t + 1) & 1];
        float2 hv = make_float2(h0v, h1v);
        __stcg(reinterpret_cast<float2*>(hout + b * NH + colbase + c0), hv);

        __threadfence();
        __syncthreads();
        if (tid == 0) atomicAdd(&g_count, 1);
    }

    // emit this thread's cell state
    g_c[b * NH + colbase + c0]     = c_reg0;
    g_c[b * NH + colbase + c0 + 1] = c_reg1;
}

// ---------------------------------------------------------------------------
// Head: out = h_final @ W_lin + b_lin; also emit h_t and c_t. Final h in g_h[0].
__global__ __launch_bounds__(256) void final_kernel(const float* __restrict__ Wl,
                                                    const float* __restrict__ bl,
                                                    float* __restrict__ out,
                                                    int out_size) {
    const float* h = g_h[0];
    if (blockIdx.x == 0) {
        for (int idx = threadIdx.x; idx < NB * NO; idx += blockDim.x) {
            int b = idx / NO, o = idx % NO;
            float s = bl[o];
            #pragma unroll 8
            for (int k = 0; k < NH; k++) s += h[b * NH + k] * Wl[k * NO + o];
            if (idx < out_size) out[idx] = s;
        }
    }
    int gidx   = blockIdx.x * blockDim.x + threadIdx.x;
    int stride = gridDim.x * blockDim.x;
    for (int i = gidx; i < NB * NH; i += stride) {
        if (NB * NO + i < out_size)           out[NB * NO + i] = h[i];
        if (NB * NO + NB * NH + i < out_size) out[NB * NO + NB * NH + i] = g_c[i];
    }
}

// ---------------------------------------------------------------------------
extern "C" void kernel_launch(void* const* d_in, const int* in_sizes, int n_in,
                              void* d_out, int out_size) {
    const int*   x   = (const int*)  d_in[0];
    const float* emb = (const float*)d_in[1];
    const float* Wfx = (const float*)d_in[2];
    const float* Wfh = (const float*)d_in[3];
    const float* bf  = (const float*)d_in[4];
    const float* Wix = (const float*)d_in[5];
    const float* Wih = (const float*)d_in[6];
    const float* bi  = (const float*)d_in[7];
    const float* Wgx = (const float*)d_in[8];
    const float* Wgh = (const float*)d_in[9];
    const float* bg  = (const float*)d_in[10];
    const float* Wox = (const float*)d_in[11];
    const float* Woh = (const float*)d_in[12];
    const float* bo  = (const float*)d_in[13];
    const float* Wl  = (const float*)d_in[14];
    const float* bl  = (const float*)d_in[15];
    float* out = (float*)d_out;

    static const int pre_smem = 8192 + 2 * 128 * 36 * 4 + 2 * 32 * 132 * 4;     // 78848
    static const int rec_smem = (512 * 40 + 64 * 520 + 64 * 36) * 4;            // 224256
    cudaFuncSetAttribute(pre_kernel, cudaFuncAttributeMaxDynamicSharedMemorySize, pre_smem);
    cudaFuncSetAttribute(rec_kernel, cudaFuncAttributeMaxDynamicSharedMemorySize, rec_smem);

    init_state<<<(NB * NH + 255) / 256, 256>>>();

    dim3 gpre(16, 128);
    pre_kernel<<<gpre, 256, pre_smem>>>(x, emb, Wfx, Wix, Wgx, Wox);

    rec_kernel<<<64, 256, rec_smem>>>(Wfh, Wih, Wgh, Woh, bf, bi, bg, bo);

    final_kernel<<<132, 256>>>(Wl, bl, out, out_size);
}

// round 5
// speedup vs baseline: 2.6521x; 1.2315x over previous
#include <cuda_runtime.h>
#include <mma.h>
#include <cstdint>

using namespace nvcuda;

#define NB 64
#define NP 16
#define NT 256
#define NI 256
#define NH 512
#define NO 5
#define NK (NP*NI)   /* 4096 */
#define NV 50000

// Scratch (device globals per harness rules)
__device__ float g_pre[4][NT][NB][NH];   // [gate][t][b][h]
__device__ float g_embT[NV * NI];        // tf32-RN rounded embedding table
__device__ float g_Wc[4][NK][NH];        // tf32-RN rounded x-weights (natural layout)
__device__ float g_h[2][NB*NH];
__device__ float g_c[NB*NH];
__device__ int   g_count;

__device__ __forceinline__ uint32_t smem_u32(const void* p) {
    uint32_t a;
    asm("{ .reg .u64 t; cvta.to.shared.u64 t, %1; cvt.u32.u64 %0, t; }" : "=r"(a) : "l"(p));
    return a;
}
#define CP_ASYNC_16(dst, src) \
    asm volatile("cp.async.cg.shared.global [%0], [%1], 16;" :: "r"(dst), "l"(src))
#define CP_ASYNC_16_PRED(dst, src, nbytes) \
    asm volatile("cp.async.cg.shared.global [%0], [%1], 16, %2;" :: "r"(dst), "l"(src), "r"(nbytes))
#define CP_COMMIT() asm volatile("cp.async.commit_group;" ::: "memory")
#define CP_WAIT(n)  asm volatile("cp.async.wait_group %0;" :: "n"(n) : "memory")

// ===================== prep: tf32-RN rounding =====================
__global__ __launch_bounds__(256) void convert_emb(const float* __restrict__ emb) {
    long idx = (long)blockIdx.x * blockDim.x + threadIdx.x;
    long n = (long)NV * NI;
    for (; idx < n; idx += (long)gridDim.x * blockDim.x)
        g_embT[idx] = wmma::__float_to_tf32(emb[idx]);
}
__global__ __launch_bounds__(256) void convert_wx(const float* __restrict__ w0,
                                                  const float* __restrict__ w1,
                                                  const float* __restrict__ w2,
                                                  const float* __restrict__ w3) {
    const float* W = (blockIdx.y == 0) ? w0 : (blockIdx.y == 1) ? w1 : (blockIdx.y == 2) ? w2 : w3;
    long idx = (long)blockIdx.x * blockDim.x + threadIdx.x;
    long n = (long)NK * NH;
    for (; idx < n; idx += (long)gridDim.x * blockDim.x)
        g_Wc[blockIdx.y][0][idx] = wmma::__float_to_tf32(W[idx]);
}

__global__ __launch_bounds__(256) void init_state() {
    int idx = blockIdx.x * blockDim.x + threadIdx.x;
    if (idx < NB * NH) { g_h[0][idx] = 0.f; }
    if (idx == 0) g_count = 0;
}

// ===================== pre-activation GEMM =====================
// CTA: M=128 (2 t x 64 b) x N=256, K=4096 in 128 slabs of 32. 3-stage cp.async.
// 8 warps, warp tile 64x64 (2 m-warps x 4 n-warps).
#define A_LD 36
#define B_LD 264
#define A_BYTES (128 * A_LD * 4)            /* 18432 */
#define B_BYTES (32 * B_LD * 4)             /* 33792 */
#define STAGE_BYTES (A_BYTES + B_BYTES)     /* 52224 */
#define TOK_BYTES 8192
#define PRE_SMEM (TOK_BYTES + 3 * STAGE_BYTES)  /* 164864 */

__global__ __launch_bounds__(256) void pre_kernel(const int* __restrict__ x) {
    extern __shared__ char smem[];
    int* sTok = (int*)smem;
    const uint32_t stage0 = smem_u32(smem + TOK_BYTES);

    const int tid  = threadIdx.x;
    const int gate = blockIdx.x >> 1;
    const int h0   = (blockIdx.x & 1) * 256;
    const int t0   = blockIdx.y * 2;

    // tokens: [tt][p][b]
    #pragma unroll
    for (int e = 0; e < 8; e++) {
        int idx = e * 256 + tid;
        int tt = idx >> 10, rem = idx & 1023;
        int p = rem >> 6, b = rem & 63;
        sTok[idx] = x[b * (NP * NT) + p * NT + (t0 + tt)];
    }
    __syncthreads();

    const float* Wbase = &g_Wc[gate][0][h0];

    // per-thread static chunk coords
    const int aRow = tid >> 1;                 // A: 2 chunks/row pair... (see below)
    // A: 1024 chunks (128 rows x 8 c4); thread handles e*256+tid
    // B: 2048 chunks (32 rows x 64 c4)
    auto issue_slab = [&](int s, int st) {
        const uint32_t aB = stage0 + st * STAGE_BYTES;
        const uint32_t bB = aB + A_BYTES;
        const int p  = s >> 3;
        const int i0 = (s & 7) * 32;
        #pragma unroll
        for (int e = 0; e < 4; e++) {
            int idx = e * 256 + tid;
            int row = idx >> 3, c4 = idx & 7;
            int tok = sTok[(row >> 6) * 1024 + p * 64 + (row & 63)];
            const float* src = g_embT + (long)tok * NI + i0 + c4 * 4;
            CP_ASYNC_16_PRED(aB + (row * A_LD + c4 * 4) * 4, src, tok ? 16 : 0);
        }
        const int k0 = s * 32;
        #pragma unroll
        for (int e = 0; e < 8; e++) {
            int idx = e * 256 + tid;
            int row = idx >> 6, c4 = idx & 63;
            const float* src = Wbase + (long)(k0 + row) * NH + c4 * 4;
            CP_ASYNC_16(bB + (row * B_LD + c4 * 4) * 4, src);
        }
        CP_COMMIT();
    };
    (void)aRow;

    const int w  = tid >> 5;
    const int m0 = (w & 1) * 64;
    const int n0 = (w >> 1) * 64;

    wmma::fragment<wmma::accumulator, 16, 16, 8, float> acc[4][4];
    #pragma unroll
    for (int i = 0; i < 4; i++)
        #pragma unroll
        for (int j = 0; j < 4; j++) wmma::fill_fragment(acc[i][j], 0.f);

    issue_slab(0, 0);
    issue_slab(1, 1);

    for (int s = 0; s < 128; s++) {
        if (s + 2 < 128) issue_slab(s + 2, (s + 2) % 3);
        else CP_COMMIT();                       // keep group count fixed
        CP_WAIT(2);
        __syncthreads();

        const char* base = smem + TOK_BYTES + (s % 3) * STAGE_BYTES;
        const float* bA = (const float*)base;
        const float* bB = (const float*)(base + A_BYTES);

        #pragma unroll
        for (int kk = 0; kk < 4; kk++) {
            wmma::fragment<wmma::matrix_a, 16, 16, 8, wmma::precision::tf32, wmma::row_major> fa[4];
            wmma::fragment<wmma::matrix_b, 16, 16, 8, wmma::precision::tf32, wmma::row_major> fb[4];
            #pragma unroll
            for (int i = 0; i < 4; i++)
                wmma::load_matrix_sync(fa[i], bA + (m0 + i * 16) * A_LD + kk * 8, A_LD);
            #pragma unroll
            for (int j = 0; j < 4; j++)
                wmma::load_matrix_sync(fb[j], bB + (kk * 8) * B_LD + n0 + j * 16, B_LD);
            #pragma unroll
            for (int i = 0; i < 4; i++)
                #pragma unroll
                for (int j = 0; j < 4; j++)
                    wmma::mma_sync(acc[i][j], fa[i], fb[j], acc[i][j]);
        }
        __syncthreads();
    }

    #pragma unroll
    for (int i = 0; i < 4; i++) {
        int m = m0 + i * 16;
        int t = t0 + (m >> 6);
        int b0 = m & 63;
        #pragma unroll
        for (int j = 0; j < 4; j++)
            wmma::store_matrix_sync(&g_pre[gate][t][b0][h0 + n0 + j * 16],
                                    acc[i][j], NH, wmma::mem_row_major);
    }
}

// ===================== persistent recurrence (known-good) =====================
__global__ __launch_bounds__(256) void rec_kernel(const float* __restrict__ Wfh,
                                                  const float* __restrict__ Wih,
                                                  const float* __restrict__ Wgh,
                                                  const float* __restrict__ Woh,
                                                  const float* __restrict__ bfp,
                                                  const float* __restrict__ bip,
                                                  const float* __restrict__ bgp,
                                                  const float* __restrict__ bop) {
    extern __shared__ float sm[];
    float* sW   = sm;                    // [512][40]
    float* sH   = sW + 512 * 40;         // [64][520]
    float* sAcc = sH + 64 * 520;         // [64][36]

    const int cta = blockIdx.x;
    const int tid = threadIdx.x;
    const int colbase = cta * 8;

    {
        const float* Wp[4] = {Wfh, Wih, Wgh, Woh};
        #pragma unroll 8
        for (int e = 0; e < 64; e++) {
            int idx = e * 256 + tid;
            int row = idx >> 5, c = idx & 31;
            float v = Wp[c >> 3][row * NH + colbase + (c & 7)];
            sW[row * 40 + c] = wmma::__float_to_tf32(v);
        }
    }

    const int b  = tid >> 2;
    const int c0 = (2 * tid) & 7;
    const float bf0 = bfp[colbase + c0], bf1 = bfp[colbase + c0 + 1];
    const float bi0 = bip[colbase + c0], bi1 = bip[colbase + c0 + 1];
    const float bg0 = bgp[colbase + c0], bg1 = bgp[colbase + c0 + 1];
    const float bo0 = bop[colbase + c0], bo1 = bop[colbase + c0 + 1];
    float c_reg0 = 0.f, c_reg1 = 0.f;

    const int w  = tid >> 5;
    const int m0 = (w >> 1) * 16;
    const int n0 = (w & 1) * 16;

    __syncthreads();

    for (int t = 0; t < NT; t++) {
        if (t > 0) {
            if (tid == 0) {
                int target = 64 * t;
                while (*(volatile int*)&g_count < target) { }
            }
            __syncthreads();
        }

        const float2 pf = *reinterpret_cast<const float2*>(&g_pre[0][t][b][colbase + c0]);
        const float2 pi = *reinterpret_cast<const float2*>(&g_pre[1][t][b][colbase + c0]);
        const float2 pg = *reinterpret_cast<const float2*>(&g_pre[2][t][b][colbase + c0]);
        const float2 po = *reinterpret_cast<const float2*>(&g_pre[3][t][b][colbase + c0]);

        const float* hin = g_h[t & 1];
        #pragma unroll 8
        for (int e = 0; e < 32; e++) {
            int idx = e * 256 + tid;
            int row = idx >> 7, c4 = idx & 127;
            float4 v = __ldcg(reinterpret_cast<const float4*>(hin + row * NH + c4 * 4));
            sH[row * 520 + c4 * 4 + 0] = wmma::__float_to_tf32(v.x);
            sH[row * 520 + c4 * 4 + 1] = wmma::__float_to_tf32(v.y);
            sH[row * 520 + c4 * 4 + 2] = wmma::__float_to_tf32(v.z);
            sH[row * 520 + c4 * 4 + 3] = wmma::__float_to_tf32(v.w);
        }
        __syncthreads();

        wmma::fragment<wmma::accumulator, 16, 16, 8, float> acc;
        wmma::fill_fragment(acc, 0.f);
        #pragma unroll 4
        for (int k = 0; k < 64; k++) {
            wmma::fragment<wmma::matrix_a, 16, 16, 8, wmma::precision::tf32, wmma::row_major> fa;
            wmma::load_matrix_sync(fa, sH + m0 * 520 + k * 8, 520);
            wmma::fragment<wmma::matrix_b, 16, 16, 8, wmma::precision::tf32, wmma::row_major> fb;
            wmma::load_matrix_sync(fb, sW + (k * 8) * 40 + n0, 40);
            wmma::mma_sync(acc, fa, fb, acc);
        }
        wmma::store_matrix_sync(sAcc + m0 * 36 + n0, acc, 36, wmma::mem_row_major);
        __syncthreads();

        float af0 = sAcc[b * 36 +  0 + c0], af1 = sAcc[b * 36 +  0 + c0 + 1];
        float ai0 = sAcc[b * 36 +  8 + c0], ai1 = sAcc[b * 36 +  8 + c0 + 1];
        float ag0 = sAcc[b * 36 + 16 + c0], ag1 = sAcc[b * 36 + 16 + c0 + 1];
        float ao0 = sAcc[b * 36 + 24 + c0], ao1 = sAcc[b * 36 + 24 + c0 + 1];

        float f0 = 1.f / (1.f + expf(-(pf.x + bf0 + af0)));
        float f1 = 1.f / (1.f + expf(-(pf.y + bf1 + af1)));
        float i0 = 1.f / (1.f + expf(-(pi.x + bi0 + ai0)));
        float i1 = 1.f / (1.f + expf(-(pi.y + bi1 + ai1)));
        float gg0 = tanhf(pg.x + bg0 + ag0);
        float gg1 = tanhf(pg.y + bg1 + ag1);
        float o0 = 1.f / (1.f + expf(-(po.x + bo0 + ao0)));
        float o1 = 1.f / (1.f + expf(-(po.y + bo1 + ao1)));

        c_reg0 = f0 * c_reg0 + i0 * gg0;
        c_reg1 = f1 * c_reg1 + i1 * gg1;
        float h0v = o0 * tanhf(c_reg0);
        float h1v = o1 * tanhf(c_reg1);

        float* hout = g_h[(t + 1) & 1];
        __stcg(reinterpret_cast<float2*>(hout + b * NH + colbase + c0), make_float2(h0v, h1v));

        __threadfence();
        __syncthreads();
        if (tid == 0) atomicAdd(&g_count, 1);
    }

    g_c[b * NH + colbase + c0]     = c_reg0;
    g_c[b * NH + colbase + c0 + 1] = c_reg1;
}

// ===================== head =====================
__global__ __launch_bounds__(256) void final_kernel(const float* __restrict__ Wl,
                                                    const float* __restrict__ bl,
                                                    float* __restrict__ out,
                                                    int out_size) {
    const float* h = g_h[0];
    if (blockIdx.x == 0) {
        for (int idx = threadIdx.x; idx < NB * NO; idx += blockDim.x) {
            int b = idx / NO, o = idx % NO;
            float s = bl[o];
            #pragma unroll 8
            for (int k = 0; k < NH; k++) s += h[b * NH + k] * Wl[k * NO + o];
            if (idx < out_size) out[idx] = s;
        }
    }
    int gidx   = blockIdx.x * blockDim.x + threadIdx.x;
    int stride = gridDim.x * blockDim.x;
    for (int i = gidx; i < NB * NH; i += stride) {
        if (NB * NO + i < out_size)           out[NB * NO + i] = h[i];
        if (NB * NO + NB * NH + i < out_size) out[NB * NO + NB * NH + i] = g_c[i];
    }
}

// ===================== launch =====================
extern "C" void kernel_launch(void* const* d_in, const int* in_sizes, int n_in,
                              void* d_out, int out_size) {
    const int*   x   = (const int*)  d_in[0];
    const float* emb = (const float*)d_in[1];
    const float* Wfx = (const float*)d_in[2];
    const float* Wfh = (const float*)d_in[3];
    const float* bf  = (const float*)d_in[4];
    const float* Wix = (const float*)d_in[5];
    const float* Wih = (const float*)d_in[6];
    const float* bi  = (const float*)d_in[7];
    const float* Wgx = (const float*)d_in[8];
    const float* Wgh = (const float*)d_in[9];
    const float* bg  = (const float*)d_in[10];
    const float* Wox = (const float*)d_in[11];
    const float* Woh = (const float*)d_in[12];
    const float* bo  = (const float*)d_in[13];
    const float* Wl  = (const float*)d_in[14];
    const float* bl  = (const float*)d_in[15];
    float* out = (float*)d_out;

    static const int rec_smem = (512 * 40 + 64 * 520 + 64 * 36) * 4;
    cudaFuncSetAttribute(pre_kernel, cudaFuncAttributeMaxDynamicSharedMemorySize, PRE_SMEM);
    cudaFuncSetAttribute(rec_kernel, cudaFuncAttributeMaxDynamicSharedMemorySize, rec_smem);

    convert_emb<<<2048, 256>>>(emb);
    convert_wx<<<dim3(1024, 4), 256>>>(Wfx, Wix, Wgx, Wox);
    init_state<<<(NB * NH + 255) / 256, 256>>>();

    pre_kernel<<<dim3(8, 128), 256, PRE_SMEM>>>(x);

    rec_kernel<<<64, 256, rec_smem>>>(Wfh, Wih, Wgh, Woh, bf, bi, bg, bo);

    final_kernel<<<132, 256>>>(Wl, bl, out, out_size);
}

// round 6
// speedup vs baseline: 7.3327x; 2.7648x over previous
#include <cuda_runtime.h>
#include <mma.h>
#include <cuda_fp16.h>
#include <cstdint>

using namespace nvcuda;

#define NB 64
#define NP 16
#define NT 256
#define NI 256
#define NH 512
#define NO 5
#define NK (NP*NI)   /* 4096 */
#define NV 50000

// Scratch (device globals per harness rules)
__device__ float  g_pre[4][NT][NB][NH];   // [gate][t][b][h]
__device__ __half g_embH[NV * NI];        // fp16 embedding table
__device__ __half g_WcH[4][NK][NH];       // fp16 x-weights (natural layout)
__device__ __half g_hh[2][NB*NH];         // fp16 hidden state ping-pong
__device__ float  g_h_final[NB*NH];
__device__ float  g_c[NB*NH];
__device__ int    g_count;

__device__ __forceinline__ uint32_t smem_u32(const void* p) {
    uint32_t a;
    asm("{ .reg .u64 t; cvta.to.shared.u64 t, %1; cvt.u32.u64 %0, t; }" : "=r"(a) : "l"(p));
    return a;
}
#define CP_ASYNC_16(dst, src) \
    asm volatile("cp.async.cg.shared.global [%0], [%1], 16;" :: "r"(dst), "l"(src))
#define CP_ASYNC_16_PRED(dst, src, nbytes) \
    asm volatile("cp.async.cg.shared.global [%0], [%1], 16, %2;" :: "r"(dst), "l"(src), "r"(nbytes))
#define CP_COMMIT() asm volatile("cp.async.commit_group;" ::: "memory")
#define CP_WAIT(n)  asm volatile("cp.async.wait_group %0;" :: "n"(n) : "memory")

// ===================== prep: fp32 -> fp16 =====================
__global__ __launch_bounds__(256) void convert_emb(const float* __restrict__ emb) {
    long idx = (long)blockIdx.x * blockDim.x + threadIdx.x;
    long n = (long)NV * NI;
    for (; idx < n; idx += (long)gridDim.x * blockDim.x)
        g_embH[idx] = __float2half_rn(emb[idx]);
}
__global__ __launch_bounds__(256) void convert_wx(const float* __restrict__ w0,
                                                  const float* __restrict__ w1,
                                                  const float* __restrict__ w2,
                                                  const float* __restrict__ w3) {
    const float* W = (blockIdx.y == 0) ? w0 : (blockIdx.y == 1) ? w1 : (blockIdx.y == 2) ? w2 : w3;
    long idx = (long)blockIdx.x * blockDim.x + threadIdx.x;
    long n = (long)NK * NH;
    for (; idx < n; idx += (long)gridDim.x * blockDim.x)
        g_WcH[blockIdx.y][0][idx] = __float2half_rn(W[idx]);
}

__global__ __launch_bounds__(256) void init_state() {
    int idx = blockIdx.x * blockDim.x + threadIdx.x;
    if (idx < NB * NH) { g_hh[0][idx] = __ushort_as_half((unsigned short)0); }
    if (idx == 0) g_count = 0;
}

// ===================== pre-activation GEMM (fp16 WMMA) =====================
// CTA: M=128 (2 t x 64 b) x N=256, K=4096 in 128 slabs of 32. 3-stage cp.async.
// 8 warps, warp tile 64x64 (2 m-warps x 4 n-warps). fp16 16x16x16 mma.
#define A_LDH 40                              /* halves */
#define B_LDH 264
#define A_BYTES (128 * A_LDH * 2)             /* 10240 */
#define B_BYTES (32 * B_LDH * 2)              /* 16896 */
#define STAGE_BYTES (A_BYTES + B_BYTES)       /* 27136 */
#define TOK_BYTES 8192
#define PRE_SMEM (TOK_BYTES + 3 * STAGE_BYTES)    /* 89600 */

__global__ __launch_bounds__(256) void pre_kernel(const int* __restrict__ x) {
    extern __shared__ char smem[];
    int* sTok = (int*)smem;
    const uint32_t stage0 = smem_u32(smem + TOK_BYTES);

    const int tid  = threadIdx.x;
    const int gate = blockIdx.x >> 1;
    const int h0   = (blockIdx.x & 1) * 256;
    const int t0   = blockIdx.y * 2;

    // tokens: [tt][p][b]
    #pragma unroll
    for (int e = 0; e < 8; e++) {
        int idx = e * 256 + tid;
        int tt = idx >> 10, rem = idx & 1023;
        int p = rem >> 6, b = rem & 63;
        sTok[idx] = x[b * (NP * NT) + p * NT + (t0 + tt)];
    }
    __syncthreads();

    const __half* Wbase = &g_WcH[gate][0][h0];

    auto issue_slab = [&](int s, int st) {
        const uint32_t aB = stage0 + st * STAGE_BYTES;
        const uint32_t bB = aB + A_BYTES;
        const int p  = s >> 3;
        const int i0 = (s & 7) * 32;
        // A: 128 rows x 32 halves = 512 chunks of 16B (8 halves) -> 2/thread
        #pragma unroll
        for (int e = 0; e < 2; e++) {
            int idx = e * 256 + tid;
            int row = idx >> 2, c8 = idx & 3;
            int tok = sTok[(row >> 6) * 1024 + p * 64 + (row & 63)];
            const __half* src = g_embH + (long)tok * NI + i0 + c8 * 8;
            CP_ASYNC_16_PRED(aB + (row * A_LDH + c8 * 8) * 2, src, tok ? 16 : 0);
        }
        // B: 32 rows x 256 halves = 1024 chunks -> 4/thread
        const int k0 = s * 32;
        #pragma unroll
        for (int e = 0; e < 4; e++) {
            int idx = e * 256 + tid;
            int row = idx >> 5, c8 = idx & 31;
            const __half* src = Wbase + (long)(k0 + row) * NH + c8 * 8;
            CP_ASYNC_16(bB + (row * B_LDH + c8 * 8) * 2, src);
        }
        CP_COMMIT();
    };

    const int w  = tid >> 5;
    const int m0 = (w & 1) * 64;
    const int n0 = (w >> 1) * 64;

    wmma::fragment<wmma::accumulator, 16, 16, 16, float> acc[4][4];
    #pragma unroll
    for (int i = 0; i < 4; i++)
        #pragma unroll
        for (int j = 0; j < 4; j++) wmma::fill_fragment(acc[i][j], 0.f);

    issue_slab(0, 0);
    issue_slab(1, 1);

    for (int s = 0; s < 128; s++) {
        if (s + 2 < 128) issue_slab(s + 2, (s + 2) % 3);
        else CP_COMMIT();
        CP_WAIT(2);
        __syncthreads();

        const char* base = smem + TOK_BYTES + (s % 3) * STAGE_BYTES;
        const __half* bA = (const __half*)base;
        const __half* bB = (const __half*)(base + A_BYTES);

        #pragma unroll
        for (int kk = 0; kk < 2; kk++) {            // two k16 steps per slab
            wmma::fragment<wmma::matrix_a, 16, 16, 16, __half, wmma::row_major> fa[4];
            wmma::fragment<wmma::matrix_b, 16, 16, 16, __half, wmma::row_major> fb[4];
            #pragma unroll
            for (int i = 0; i < 4; i++)
                wmma::load_matrix_sync(fa[i], bA + (m0 + i * 16) * A_LDH + kk * 16, A_LDH);
            #pragma unroll
            for (int j = 0; j < 4; j++)
                wmma::load_matrix_sync(fb[j], bB + (kk * 16) * B_LDH + n0 + j * 16, B_LDH);
            #pragma unroll
            for (int i = 0; i < 4; i++)
                #pragma unroll
                for (int j = 0; j < 4; j++)
                    wmma::mma_sync(acc[i][j], fa[i], fb[j], acc[i][j]);
        }
        __syncthreads();
    }

    #pragma unroll
    for (int i = 0; i < 4; i++) {
        int m = m0 + i * 16;
        int t = t0 + (m >> 6);
        int b0 = m & 63;
        #pragma unroll
        for (int j = 0; j < 4; j++)
            wmma::store_matrix_sync(&g_pre[gate][t][b0][h0 + n0 + j * 16],
                                    acc[i][j], NH, wmma::mem_row_major);
    }
}

// ===================== persistent recurrence (fp16 GEMM) =====================
// 64 CTAs x 256 threads. CTA owns 8 h-cols x 4 gates (N=32). W in smem fp16,
// h state fp16 ping-pong in L2, c in regs, release/acquire global barrier.
#define SW_BYTES (512 * 40 * 2)               /* 40960 */
#define SH_BYTES (64 * 528 * 2)               /* 67584 */
#define SACC_OFF (SW_BYTES + SH_BYTES)        /* 108544 */
#define REC_SMEM (SACC_OFF + 64 * 36 * 4)     /* 117760 */

__global__ __launch_bounds__(256) void rec_kernel(const float* __restrict__ Wfh,
                                                  const float* __restrict__ Wih,
                                                  const float* __restrict__ Wgh,
                                                  const float* __restrict__ Woh,
                                                  const float* __restrict__ bfp,
                                                  const float* __restrict__ bip,
                                                  const float* __restrict__ bgp,
                                                  const float* __restrict__ bop) {
    extern __shared__ char smraw[];
    __half* sW   = (__half*)smraw;                 // [512][40], col = gate*8+c
    __half* sH   = (__half*)(smraw + SW_BYTES);    // [64][528]
    float*  sAcc = (float*)(smraw + SACC_OFF);     // [64][36]

    const int cta = blockIdx.x;
    const int tid = threadIdx.x;
    const int colbase = cta * 8;
    int* const pcnt = &g_count;

    {
        const float* Wp[4] = {Wfh, Wih, Wgh, Woh};
        #pragma unroll 8
        for (int e = 0; e < 64; e++) {
            int idx = e * 256 + tid;
            int row = idx >> 5, c = idx & 31;
            float v = Wp[c >> 3][row * NH + colbase + (c & 7)];
            sW[row * 40 + c] = __float2half_rn(v);
        }
    }

    const int b  = tid >> 2;
    const int c0 = (2 * tid) & 7;
    const float bf0 = bfp[colbase + c0], bf1 = bfp[colbase + c0 + 1];
    const float bi0 = bip[colbase + c0], bi1 = bip[colbase + c0 + 1];
    const float bg0 = bgp[colbase + c0], bg1 = bgp[colbase + c0 + 1];
    const float bo0 = bop[colbase + c0], bo1 = bop[colbase + c0 + 1];
    float c_reg0 = 0.f, c_reg1 = 0.f;

    const int w  = tid >> 5;
    const int m0 = (w >> 1) * 16;
    const int n0 = (w & 1) * 16;

    __syncthreads();

    for (int t = 0; t < NT; t++) {
        if (t > 0) {
            if (tid == 0) {
                int target = 64 * t, v;
                do {
                    asm volatile("ld.acquire.gpu.b32 %0, [%1];" : "=r"(v) : "l"(pcnt) : "memory");
                } while (v < target);
            }
            __syncthreads();
        }

        const float2 pf = *reinterpret_cast<const float2*>(&g_pre[0][t][b][colbase + c0]);
        const float2 pi = *reinterpret_cast<const float2*>(&g_pre[1][t][b][colbase + c0]);
        const float2 pg = *reinterpret_cast<const float2*>(&g_pre[2][t][b][colbase + c0]);
        const float2 po = *reinterpret_cast<const float2*>(&g_pre[3][t][b][colbase + c0]);

        // stage h (fp16, 64KB) : 4096 16B chunks -> 16/thread
        const __half* hin = g_hh[t & 1];
        #pragma unroll 8
        for (int e = 0; e < 16; e++) {
            int idx = e * 256 + tid;
            int row = idx >> 6, c = idx & 63;
            uint4 v = __ldcg(reinterpret_cast<const uint4*>(hin + row * NH + c * 8));
            *reinterpret_cast<uint4*>(sH + row * 528 + c * 8) = v;
        }
        __syncthreads();

        // GEMM: [64x512] @ [512x32], fp16 16x16x16
        wmma::fragment<wmma::accumulator, 16, 16, 16, float> acc;
        wmma::fill_fragment(acc, 0.f);
        #pragma unroll 8
        for (int k = 0; k < 32; k++) {
            wmma::fragment<wmma::matrix_a, 16, 16, 16, __half, wmma::row_major> fa;
            wmma::load_matrix_sync(fa, sH + m0 * 528 + k * 16, 528);
            wmma::fragment<wmma::matrix_b, 16, 16, 16, __half, wmma::row_major> fb;
            wmma::load_matrix_sync(fb, sW + (k * 16) * 40 + n0, 40);
            wmma::mma_sync(acc, fa, fb, acc);
        }
        wmma::store_matrix_sync(sAcc + m0 * 36 + n0, acc, 36, wmma::mem_row_major);
        __syncthreads();

        float af0 = sAcc[b * 36 +  0 + c0], af1 = sAcc[b * 36 +  0 + c0 + 1];
        float ai0 = sAcc[b * 36 +  8 + c0], ai1 = sAcc[b * 36 +  8 + c0 + 1];
        float ag0 = sAcc[b * 36 + 16 + c0], ag1 = sAcc[b * 36 + 16 + c0 + 1];
        float ao0 = sAcc[b * 36 + 24 + c0], ao1 = sAcc[b * 36 + 24 + c0 + 1];

        float f0 = 1.f / (1.f + expf(-(pf.x + bf0 + af0)));
        float f1 = 1.f / (1.f + expf(-(pf.y + bf1 + af1)));
        float i0 = 1.f / (1.f + expf(-(pi.x + bi0 + ai0)));
        float i1 = 1.f / (1.f + expf(-(pi.y + bi1 + ai1)));
        float gg0 = tanhf(pg.x + bg0 + ag0);
        float gg1 = tanhf(pg.y + bg1 + ag1);
        float o0 = 1.f / (1.f + expf(-(po.x + bo0 + ao0)));
        float o1 = 1.f / (1.f + expf(-(po.y + bo1 + ao1)));

        c_reg0 = f0 * c_reg0 + i0 * gg0;
        c_reg1 = f1 * c_reg1 + i1 * gg1;
        float h0v = o0 * tanhf(c_reg0);
        float h1v = o1 * tanhf(c_reg1);

        __half* hout = g_hh[(t + 1) & 1];
        __half2 hv = __floats2half2_rn(h0v, h1v);
        __stcg(reinterpret_cast<__half2*>(hout + b * NH + colbase + c0), hv);
        if (t == NT - 1) {
            g_h_final[b * NH + colbase + c0]     = h0v;
            g_h_final[b * NH + colbase + c0 + 1] = h1v;
        }

        __syncthreads();                 // all stores in CTA done
        if (tid == 0) {
            asm volatile("red.release.gpu.add.s32 [%0], %1;" :: "l"(pcnt), "r"(1) : "memory");
        }
    }

    g_c[b * NH + colbase + c0]     = c_reg0;
    g_c[b * NH + colbase + c0 + 1] = c_reg1;
}

// ===================== head =====================
__global__ __launch_bounds__(256) void final_kernel(const float* __restrict__ Wl,
                                                    const float* __restrict__ bl,
                                                    float* __restrict__ out,
                                                    int out_size) {
    const float* h = g_h_final;
    if (blockIdx.x == 0) {
        for (int idx = threadIdx.x; idx < NB * NO; idx += blockDim.x) {
            int b = idx / NO, o = idx % NO;
            float s = bl[o];
            #pragma unroll 8
            for (int k = 0; k < NH; k++) s += h[b * NH + k] * Wl[k * NO + o];
            if (idx < out_size) out[idx] = s;
        }
    }
    int gidx   = blockIdx.x * blockDim.x + threadIdx.x;
    int stride = gridDim.x * blockDim.x;
    for (int i = gidx; i < NB * NH; i += stride) {
        if (NB * NO + i < out_size)           out[NB * NO + i] = h[i];
        if (NB * NO + NB * NH + i < out_size) out[NB * NO + NB * NH + i] = g_c[i];
    }
}

// ===================== launch =====================
extern "C" void kernel_launch(void* const* d_in, const int* in_sizes, int n_in,
                              void* d_out, int out_size) {
    const int*   x   = (const int*)  d_in[0];
    const float* emb = (const float*)d_in[1];
    const float* Wfx = (const float*)d_in[2];
    const float* Wfh = (const float*)d_in[3];
    const float* bf  = (const float*)d_in[4];
    const float* Wix = (const float*)d_in[5];
    const float* Wih = (const float*)d_in[6];
    const float* bi  = (const float*)d_in[7];
    const float* Wgx = (const float*)d_in[8];
    const float* Wgh = (const float*)d_in[9];
    const float* bg  = (const float*)d_in[10];
    const float* Wox = (const float*)d_in[11];
    const float* Woh = (const float*)d_in[12];
    const float* bo  = (const float*)d_in[13];
    const float* Wl  = (const float*)d_in[14];
    const float* bl  = (const float*)d_in[15];
    float* out = (float*)d_out;

    cudaFuncSetAttribute(pre_kernel, cudaFuncAttributeMaxDynamicSharedMemorySize, PRE_SMEM);
    cudaFuncSetAttribute(rec_kernel, cudaFuncAttributeMaxDynamicSharedMemorySize, REC_SMEM);

    convert_emb<<<2048, 256>>>(emb);
    convert_wx<<<dim3(1024, 4), 256>>>(Wfx, Wix, Wgx, Wox);
    init_state<<<(NB * NH + 255) / 256, 256>>>();

    pre_kernel<<<dim3(8, 128), 256, PRE_SMEM>>>(x);

    rec_kernel<<<64, 256, REC_SMEM>>>(Wfh, Wih, Wgh, Woh, bf, bi, bg, bo);

    final_kernel<<<132, 256>>>(Wl, bl, out, out_size);
}

// round 8
// speedup vs baseline: 9.3703x; 1.2779x over previous
#include <cuda_runtime.h>
#include <mma.h>
#include <cuda_fp16.h>
#include <cstdint>

using namespace nvcuda;

#define NB 64
#define NP 16
#define NT 256
#define NI 256
#define NH 512
#define NO 5
#define NK (NP*NI)   /* 4096 */
#define NV 50000

// Scratch (device globals per harness rules)
__device__ float  g_pre[4][NT][NB][NH];   // [gate][t][b][h]
__device__ __half g_embH[NV * NI];        // fp16 embedding table
__device__ __half g_WcH[4][NK][NH];       // fp16 x-weights (natural layout)
__device__ __half g_hh[2][NB*NH];         // fp16 hidden state ping-pong
__device__ float  g_h_final[NB*NH];
__device__ float  g_c[NB*NH];
__device__ int    g_count;

__device__ __forceinline__ uint32_t smem_u32(const void* p) {
    uint32_t a;
    asm("{ .reg .u64 t; cvta.to.shared.u64 t, %1; cvt.u32.u64 %0, t; }" : "=r"(a) : "l"(p));
    return a;
}
#define CP_ASYNC_16(dst, src) \
    asm volatile("cp.async.cg.shared.global [%0], [%1], 16;" :: "r"(dst), "l"(src))
#define CP_ASYNC_16_PRED(dst, src, nbytes) \
    asm volatile("cp.async.cg.shared.global [%0], [%1], 16, %2;" :: "r"(dst), "l"(src), "r"(nbytes))
#define CP_COMMIT() asm volatile("cp.async.commit_group;" ::: "memory")
#define CP_WAIT(n)  asm volatile("cp.async.wait_group %0;" :: "n"(n) : "memory")
#define CP_WAIT_ALL() asm volatile("cp.async.wait_all;" ::: "memory")

// ===================== prep: fp32 -> fp16 =====================
__global__ __launch_bounds__(256) void convert_emb(const float* __restrict__ emb) {
    long idx = (long)blockIdx.x * blockDim.x + threadIdx.x;
    long n = (long)NV * NI;
    for (; idx < n; idx += (long)gridDim.x * blockDim.x)
        g_embH[idx] = __float2half_rn(emb[idx]);
}
__global__ __launch_bounds__(256) void convert_wx(const float* __restrict__ w0,
                                                  const float* __restrict__ w1,
                                                  const float* __restrict__ w2,
                                                  const float* __restrict__ w3) {
    const float* W = (blockIdx.y == 0) ? w0 : (blockIdx.y == 1) ? w1 : (blockIdx.y == 2) ? w2 : w3;
    long idx = (long)blockIdx.x * blockDim.x + threadIdx.x;
    long n = (long)NK * NH;
    for (; idx < n; idx += (long)gridDim.x * blockDim.x)
        g_WcH[blockIdx.y][0][idx] = __float2half_rn(W[idx]);
}

__global__ __launch_bounds__(256) void init_state() {
    int idx = blockIdx.x * blockDim.x + threadIdx.x;
    if (idx < NB * NH) { g_hh[0][idx] = __ushort_as_half((unsigned short)0); }
    if (idx == 0) g_count = 0;
}

// ===================== pre-activation GEMM (fp16 WMMA) =====================
// CTA: M=128 (2 t x 64 b) x N=256, K=4096 in 64 slabs of 64. 3-stage cp.async.
// 8 warps, warp tile 64x64 (2 m-warps x 4 n-warps). fp16 16x16x16 mma.
#define A_LDH 72                              /* halves */
#define B_LDH 264
#define A_BYTES (128 * A_LDH * 2)             /* 18432 */
#define B_BYTES (64 * B_LDH * 2)              /* 33792 */
#define STAGE_BYTES (A_BYTES + B_BYTES)       /* 52224 */
#define TOK_BYTES 8192
#define PRE_SMEM (TOK_BYTES + 3 * STAGE_BYTES)    /* 164864 */

__global__ __launch_bounds__(256) void pre_kernel(const int* __restrict__ x) {
    extern __shared__ char smem[];
    int* sTok = (int*)smem;
    const uint32_t stage0 = smem_u32(smem + TOK_BYTES);

    const int tid  = threadIdx.x;
    const int gate = blockIdx.x >> 1;
    const int h0   = (blockIdx.x & 1) * 256;
    const int t0   = blockIdx.y * 2;

    // tokens: [tt][p][b]
    #pragma unroll
    for (int e = 0; e < 8; e++) {
        int idx = e * 256 + tid;
        int tt = idx >> 10, rem = idx & 1023;
        int p = rem >> 6, b = rem & 63;
        sTok[idx] = x[b * (NP * NT) + p * NT + (t0 + tt)];
    }
    __syncthreads();

    const __half* Wbase = &g_WcH[gate][0][h0];

    auto issue_slab = [&](int s, int st) {
        const uint32_t aB = stage0 + st * STAGE_BYTES;
        const uint32_t bB = aB + A_BYTES;
        const int p  = s >> 2;
        const int i0 = (s & 3) * 64;
        // A: 128 rows x 64 halves = 1024 chunks of 8 halves -> 4/thread
        #pragma unroll
        for (int e = 0; e < 4; e++) {
            int idx = e * 256 + tid;
            int row = idx >> 3, c8 = idx & 7;
            int tok = sTok[(row >> 6) * 1024 + p * 64 + (row & 63)];
            const __half* src = g_embH + (long)tok * NI + i0 + c8 * 8;
            CP_ASYNC_16_PRED(aB + (row * A_LDH + c8 * 8) * 2, src, tok ? 16 : 0);
        }
        // B: 64 rows x 256 halves = 2048 chunks -> 8/thread
        const int k0 = s * 64;
        #pragma unroll
        for (int e = 0; e < 8; e++) {
            int idx = e * 256 + tid;
            int row = idx >> 5, c8 = idx & 31;
            const __half* src = Wbase + (long)(k0 + row) * NH + c8 * 8;
            CP_ASYNC_16(bB + (row * B_LDH + c8 * 8) * 2, src);
        }
        CP_COMMIT();
    };

    const int w  = tid >> 5;
    const int m0 = (w & 1) * 64;
    const int n0 = (w >> 1) * 64;

    wmma::fragment<wmma::accumulator, 16, 16, 16, float> acc[4][4];
    #pragma unroll
    for (int i = 0; i < 4; i++)
        #pragma unroll
        for (int j = 0; j < 4; j++) wmma::fill_fragment(acc[i][j], 0.f);

    issue_slab(0, 0);
    issue_slab(1, 1);

    for (int s = 0; s < 64; s++) {
        if (s + 2 < 64) issue_slab(s + 2, (s + 2) % 3);
        else CP_COMMIT();
        CP_WAIT(2);
        __syncthreads();

        const char* base = smem + TOK_BYTES + (s % 3) * STAGE_BYTES;
        const __half* bA = (const __half*)base;
        const __half* bB = (const __half*)(base + A_BYTES);

        #pragma unroll
        for (int kk = 0; kk < 4; kk++) {            // four k16 steps per slab
            wmma::fragment<wmma::matrix_a, 16, 16, 16, __half, wmma::row_major> fa[4];
            wmma::fragment<wmma::matrix_b, 16, 16, 16, __half, wmma::row_major> fb[4];
            #pragma unroll
            for (int i = 0; i < 4; i++)
                wmma::load_matrix_sync(fa[i], bA + (m0 + i * 16) * A_LDH + kk * 16, A_LDH);
            #pragma unroll
            for (int j = 0; j < 4; j++)
                wmma::load_matrix_sync(fb[j], bB + (kk * 16) * B_LDH + n0 + j * 16, B_LDH);
            #pragma unroll
            for (int i = 0; i < 4; i++)
                #pragma unroll
                for (int j = 0; j < 4; j++)
                    wmma::mma_sync(acc[i][j], fa[i], fb[j], acc[i][j]);
        }
        __syncthreads();
    }

    #pragma unroll
    for (int i = 0; i < 4; i++) {
        int m = m0 + i * 16;
        int t = t0 + (m >> 6);
        int b0 = m & 63;
        #pragma unroll
        for (int j = 0; j < 4; j++)
            wmma::store_matrix_sync(&g_pre[gate][t][b0][h0 + n0 + j * 16],
                                    acc[i][j], NH, wmma::mem_row_major);
    }
}

// ===================== persistent recurrence (fp16, split-K, 128 CTAs) ========
// 128 CTAs x 256 threads. CTA owns 4 h-cols x 4 gates (N=16). 8 warps =
// 4 m-tiles x 2 K-halves -> A frags loaded exactly once. h staged by cp.async.
#define R_SW_LD 24                              /* halves, 16 cols + pad */
#define R_SH_LD 528
#define R_SW_BYTES (512 * R_SW_LD * 2)          /* 24576 */
#define R_SH_BYTES (64 * R_SH_LD * 2)           /* 67584 */
#define R_SACC_OFF (R_SW_BYTES + R_SH_BYTES)    /* 92160 */
#define R_ACC_LD 20
#define REC_SMEM (R_SACC_OFF + 2 * 64 * R_ACC_LD * 4)  /* 102400 */
#define RCTAS 128

__global__ __launch_bounds__(256) void rec_kernel(const float* __restrict__ Wfh,
                                                  const float* __restrict__ Wih,
                                                  const float* __restrict__ Wgh,
                                                  const float* __restrict__ Woh,
                                                  const float* __restrict__ bfp,
                                                  const float* __restrict__ bip,
                                                  const float* __restrict__ bgp,
                                                  const float* __restrict__ bop) {
    extern __shared__ char smraw[];
    __half* sW   = (__half*)smraw;                   // [512][24], col = gate*4+c
    __half* sH   = (__half*)(smraw + R_SW_BYTES);    // [64][528]
    float*  sAcc = (float*)(smraw + R_SACC_OFF);     // [2][64][20]

    const int cta = blockIdx.x;
    const int tid = threadIdx.x;
    const int colbase = cta * 4;                     // h columns owned
    int* const pcnt = &g_count;

    // Load W slice: 512 rows x 16 cols (gate*4 + c)
    {
        const float* Wp[4] = {Wfh, Wih, Wgh, Woh};
        #pragma unroll 8
        for (int e = 0; e < 32; e++) {
            int idx = e * 256 + tid;                 // 8192
            int row = idx >> 4, c = idx & 15;
            float v = Wp[c >> 2][row * NH + colbase + (c & 3)];
            sW[row * R_SW_LD + c] = __float2half_rn(v);
        }
    }

    const int b  = tid >> 2;                         // 0..63
    const int c  = tid & 3;                          // 0..3
    const float bfv = bfp[colbase + c];
    const float biv = bip[colbase + c];
    const float bgv = bgp[colbase + c];
    const float bov = bop[colbase + c];
    float c_reg = 0.f;

    const int w  = tid >> 5;
    const int m0 = (w & 3) * 16;                     // m-tile
    const int kh = w >> 2;                           // K-half (0/1)

    __syncthreads();

    for (int t = 0; t < NT; t++) {
        if (t > 0) {
            if (tid == 0) {
                int target = RCTAS * t, v;
                do {
                    asm volatile("ld.acquire.gpu.b32 %0, [%1];" : "=r"(v) : "l"(pcnt) : "memory");
                } while (v < target);
            }
            __syncthreads();
        }

        // prefetch this thread's pre-activations (independent of h)
        const float pf = g_pre[0][t][b][colbase + c];
        const float pi = g_pre[1][t][b][colbase + c];
        const float pg = g_pre[2][t][b][colbase + c];
        const float po = g_pre[3][t][b][colbase + c];

        // stage h (fp16, 64KB) via cp.async: 4096 chunks -> 16/thread
        const __half* hin = g_hh[t & 1];
        const uint32_t sHa = smem_u32(sH);
        #pragma unroll
        for (int e = 0; e < 16; e++) {
            int idx = e * 256 + tid;
            int row = idx >> 6, cc = idx & 63;
            CP_ASYNC_16(sHa + (row * R_SH_LD + cc * 8) * 2,
                        hin + row * NH + cc * 8);
        }
        CP_COMMIT();
        CP_WAIT_ALL();
        __syncthreads();

        // GEMM: [64x512] @ [512x16], split-K: warp (m0, kh) does 16 k16-steps
        wmma::fragment<wmma::accumulator, 16, 16, 16, float> acc;
        wmma::fill_fragment(acc, 0.f);
        #pragma unroll 8
        for (int i = 0; i < 16; i++) {
            int k16 = kh * 16 + i;
            wmma::fragment<wmma::matrix_a, 16, 16, 16, __half, wmma::row_major> fa;
            wmma::load_matrix_sync(fa, sH + m0 * R_SH_LD + k16 * 16, R_SH_LD);
            wmma::fragment<wmma::matrix_b, 16, 16, 16, __half, wmma::row_major> fb;
            wmma::load_matrix_sync(fb, sW + (k16 * 16) * R_SW_LD, R_SW_LD);
            wmma::mma_sync(acc, fa, fb, acc);
        }
        wmma::store_matrix_sync(sAcc + (kh * 64 + m0) * R_ACC_LD, acc,
                                R_ACC_LD, wmma::mem_row_major);
        __syncthreads();

        // Elementwise: thread handles (b, c) for all 4 gates
        const float* a0 = sAcc + b * R_ACC_LD;
        const float* a1 = sAcc + (64 + b) * R_ACC_LD;
        float af = a0[0 * 4 + c] + a1[0 * 4 + c];
        float ai = a0[1 * 4 + c] + a1[1 * 4 + c];
        float ag = a0[2 * 4 + c] + a1[2 * 4 + c];
        float ao = a0[3 * 4 + c] + a1[3 * 4 + c];

        float f = 1.f / (1.f + expf(-(pf + bfv + af)));
        float i = 1.f / (1.f + expf(-(pi + biv + ai)));
        float g = tanhf(pg + bgv + ag);
        float o = 1.f / (1.f + expf(-(po + bov + ao)));

        c_reg = f * c_reg + i * g;
        float hv = o * tanhf(c_reg);

        __half* hout = g_hh[(t + 1) & 1];
        __stcg(hout + b * NH + colbase + c, __float2half_rn(hv));
        if (t == NT - 1) g_h_final[b * NH + colbase + c] = hv;

        __syncthreads();                 // all stores in CTA done
        if (tid == 0) {
            asm volatile("red.release.gpu.add.s32 [%0], %1;" :: "l"(pcnt), "r"(1) : "memory");
        }
    }

    g_c[b * NH + colbase + c] = c_reg;
}

// ===================== head =====================
__global__ __launch_bounds__(256) void final_kernel(const float* __restrict__ Wl,
                                                    const float* __restrict__ bl,
                                                    float* __restrict__ out,
                                                    int out_size) {
    const float* h = g_h_final;
    if (blockIdx.x == 0) {
        for (int idx = threadIdx.x; idx < NB * NO; idx += blockDim.x) {
            int b = idx / NO, o = idx % NO;
            float s = bl[o];
            #pragma unroll 8
            for (int k = 0; k < NH; k++) s += h[b * NH + k] * Wl[k * NO + o];
            if (idx < out_size) out[idx] = s;
        }
    }
    int gidx   = blockIdx.x * blockDim.x + threadIdx.x;
    int stride = gridDim.x * blockDim.x;
    for (int i = gidx; i < NB * NH; i += stride) {
        if (NB * NO + i < out_size)           out[NB * NO + i] = h[i];
        if (NB * NO + NB * NH + i < out_size) out[NB * NO + NB * NH + i] = g_c[i];
    }
}

// ===================== launch =====================
extern "C" void kernel_launch(void* const* d_in, const int* in_sizes, int n_in,
                              void* d_out, int out_size) {
    const int*   x   = (const int*)  d_in[0];
    const float* emb = (const float*)d_in[1];
    const float* Wfx = (const float*)d_in[2];
    const float* Wfh = (const float*)d_in[3];
    const float* bf  = (const float*)d_in[4];
    const float* Wix = (const float*)d_in[5];
    const float* Wih = (const float*)d_in[6];
    const float* bi  = (const float*)d_in[7];
    const float* Wgx = (const float*)d_in[8];
    const float* Wgh = (const float*)d_in[9];
    const float* bg  = (const float*)d_in[10];
    const float* Wox = (const float*)d_in[11];
    const float* Woh = (const float*)d_in[12];
    const float* bo  = (const float*)d_in[13];
    const float* Wl  = (const float*)d_in[14];
    const float* bl  = (const float*)d_in[15];
    float* out = (float*)d_out;

    cudaFuncSetAttribute(pre_kernel, cudaFuncAttributeMaxDynamicSharedMemorySize, PRE_SMEM);
    cudaFuncSetAttribute(rec_kernel, cudaFuncAttributeMaxDynamicSharedMemorySize, REC_SMEM);

    convert_emb<<<2048, 256>>>(emb);
    convert_wx<<<dim3(1024, 4), 256>>>(Wfx, Wix, Wgx, Wox);
    init_state<<<(NB * NH + 255) / 256, 256>>>();

    pre_kernel<<<dim3(8, 128), 256, PRE_SMEM>>>(x);

    rec_kernel<<<RCTAS, 256, REC_SMEM>>>(Wfh, Wih, Wgh, Woh, bf, bi, bg, bo);

    final_kernel<<<132, 256>>>(Wl, bl, out, out_size);
}

// round 9
// speedup vs baseline: 9.5157x; 1.0155x over previous
#include <cuda_runtime.h>
#include <mma.h>
#include <cuda_fp16.h>
#include <cstdint>

using namespace nvcuda;

#define NB 64
#define NP 16
#define NT 256
#define NI 256
#define NH 512
#define NO 5
#define NK (NP*NI)   /* 4096 */
#define NV 50000

// Scratch (device globals per harness rules)
__device__ float  g_pre[4][NT][NB][NH];   // [gate][t][b][h]
__device__ __half g_embH[NV * NI];        // fp16 embedding table
__device__ __half g_WcH[4][NK][NH];       // fp16 x-weights (natural layout)
__device__ __half g_hh[2][NB*NH];         // fp16 hidden state ping-pong
__device__ float  g_h_final[NB*NH];
__device__ float  g_c[NB*NH];
__device__ int    g_count;

__device__ __forceinline__ uint32_t smem_u32(const void* p) {
    uint32_t a;
    asm("{ .reg .u64 t; cvta.to.shared.u64 t, %1; cvt.u32.u64 %0, t; }" : "=r"(a) : "l"(p));
    return a;
}
#define CP_ASYNC_16(dst, src) \
    asm volatile("cp.async.cg.shared.global [%0], [%1], 16;" :: "r"(dst), "l"(src))
#define CP_ASYNC_16_PRED(dst, src, nbytes) \
    asm volatile("cp.async.cg.shared.global [%0], [%1], 16, %2;" :: "r"(dst), "l"(src), "r"(nbytes))
#define CP_COMMIT() asm volatile("cp.async.commit_group;" ::: "memory")
#define CP_WAIT(n)  asm volatile("cp.async.wait_group %0;" :: "n"(n) : "memory")
#define CP_WAIT_ALL() asm volatile("cp.async.wait_all;" ::: "memory")

#define LDMATRIX_X4(a0, a1, a2, a3, addr) \
    asm volatile("ldmatrix.sync.aligned.m8n8.x4.shared.b16 {%0,%1,%2,%3}, [%4];" \
                 : "=r"(a0), "=r"(a1), "=r"(a2), "=r"(a3) : "r"(addr))

#define MMA_16816(d, a0, a1, a2, a3, b0, b1) \
    asm volatile("mma.sync.aligned.m16n8k16.row.col.f32.f16.f16.f32 " \
                 "{%0,%1,%2,%3}, {%4,%5,%6,%7}, {%8,%9}, {%0,%1,%2,%3};" \
                 : "+f"((d)[0]), "+f"((d)[1]), "+f"((d)[2]), "+f"((d)[3]) \
                 : "r"(a0), "r"(a1), "r"(a2), "r"(a3), "r"(b0), "r"(b1))

// ===================== prep: fp32 -> fp16 =====================
__global__ __launch_bounds__(256) void convert_emb(const float* __restrict__ emb) {
    long idx = (long)blockIdx.x * blockDim.x + threadIdx.x;
    long n = (long)NV * NI;
    for (; idx < n; idx += (long)gridDim.x * blockDim.x)
        g_embH[idx] = __float2half_rn(emb[idx]);
}
__global__ __launch_bounds__(256) void convert_wx(const float* __restrict__ w0,
                                                  const float* __restrict__ w1,
                                                  const float* __restrict__ w2,
                                                  const float* __restrict__ w3) {
    const float* W = (blockIdx.y == 0) ? w0 : (blockIdx.y == 1) ? w1 : (blockIdx.y == 2) ? w2 : w3;
    long idx = (long)blockIdx.x * blockDim.x + threadIdx.x;
    long n = (long)NK * NH;
    for (; idx < n; idx += (long)gridDim.x * blockDim.x)
        g_WcH[blockIdx.y][0][idx] = __float2half_rn(W[idx]);
}

__global__ __launch_bounds__(256) void init_state() {
    int idx = blockIdx.x * blockDim.x + threadIdx.x;
    if (idx < NB * NH) { g_hh[0][idx] = __ushort_as_half((unsigned short)0); }
    if (idx == 0) g_count = 0;
}

// ===================== pre-activation GEMM (fp16 WMMA) =====================
// CTA: M=128 (2 t x 64 b) x N=256, K=4096 in 64 slabs of 64. 3-stage cp.async,
// single __syncthreads per slab. 8 warps, warp tile 64x64.
#define A_LDH 72                              /* halves */
#define B_LDH 264
#define A_BYTES (128 * A_LDH * 2)             /* 18432 */
#define B_BYTES (64 * B_LDH * 2)              /* 33792 */
#define STAGE_BYTES (A_BYTES + B_BYTES)       /* 52224 */
#define TOK_BYTES 8192
#define PRE_SMEM (TOK_BYTES + 3 * STAGE_BYTES)    /* 164864 */

__global__ __launch_bounds__(256) void pre_kernel(const int* __restrict__ x) {
    extern __shared__ char smem[];
    int* sTok = (int*)smem;
    const uint32_t stage0 = smem_u32(smem + TOK_BYTES);

    const int tid  = threadIdx.x;
    const int gate = blockIdx.x >> 1;
    const int h0   = (blockIdx.x & 1) * 256;
    const int t0   = blockIdx.y * 2;

    #pragma unroll
    for (int e = 0; e < 8; e++) {
        int idx = e * 256 + tid;
        int tt = idx >> 10, rem = idx & 1023;
        int p = rem >> 6, b = rem & 63;
        sTok[idx] = x[b * (NP * NT) + p * NT + (t0 + tt)];
    }
    __syncthreads();

    const __half* Wbase = &g_WcH[gate][0][h0];

    auto issue_slab = [&](int s, int st) {
        const uint32_t aB = stage0 + st * STAGE_BYTES;
        const uint32_t bB = aB + A_BYTES;
        const int p  = s >> 2;
        const int i0 = (s & 3) * 64;
        #pragma unroll
        for (int e = 0; e < 4; e++) {
            int idx = e * 256 + tid;
            int row = idx >> 3, c8 = idx & 7;
            int tok = sTok[(row >> 6) * 1024 + p * 64 + (row & 63)];
            const __half* src = g_embH + (long)tok * NI + i0 + c8 * 8;
            CP_ASYNC_16_PRED(aB + (row * A_LDH + c8 * 8) * 2, src, tok ? 16 : 0);
        }
        const int k0 = s * 64;
        #pragma unroll
        for (int e = 0; e < 8; e++) {
            int idx = e * 256 + tid;
            int row = idx >> 5, c8 = idx & 31;
            const __half* src = Wbase + (long)(k0 + row) * NH + c8 * 8;
            CP_ASYNC_16(bB + (row * B_LDH + c8 * 8) * 2, src);
        }
        CP_COMMIT();
    };

    const int w  = tid >> 5;
    const int m0 = (w & 1) * 64;
    const int n0 = (w >> 1) * 64;

    wmma::fragment<wmma::accumulator, 16, 16, 16, float> acc[4][4];
    #pragma unroll
    for (int i = 0; i < 4; i++)
        #pragma unroll
        for (int j = 0; j < 4; j++) wmma::fill_fragment(acc[i][j], 0.f);

    issue_slab(0, 0);
    issue_slab(1, 1);

    for (int s = 0; s < 64; s++) {
        CP_WAIT(1);                  // slab s complete (s+1 may be in flight)
        __syncthreads();             // everyone past reads of stage s-1
        if (s + 2 < 64) issue_slab(s + 2, (s + 2) % 3);
        else CP_COMMIT();            // keep group count uniform

        const char* base = smem + TOK_BYTES + (s % 3) * STAGE_BYTES;
        const __half* bA = (const __half*)base;
        const __half* bB = (const __half*)(base + A_BYTES);

        #pragma unroll
        for (int kk = 0; kk < 4; kk++) {
            wmma::fragment<wmma::matrix_a, 16, 16, 16, __half, wmma::row_major> fa[4];
            wmma::fragment<wmma::matrix_b, 16, 16, 16, __half, wmma::row_major> fb[4];
            #pragma unroll
            for (int i = 0; i < 4; i++)
                wmma::load_matrix_sync(fa[i], bA + (m0 + i * 16) * A_LDH + kk * 16, A_LDH);
            #pragma unroll
            for (int j = 0; j < 4; j++)
                wmma::load_matrix_sync(fb[j], bB + (kk * 16) * B_LDH + n0 + j * 16, B_LDH);
            #pragma unroll
            for (int i = 0; i < 4; i++)
                #pragma unroll
                for (int j = 0; j < 4; j++)
                    wmma::mma_sync(acc[i][j], fa[i], fb[j], acc[i][j]);
        }
    }

    #pragma unroll
    for (int i = 0; i < 4; i++) {
        int m = m0 + i * 16;
        int t = t0 + (m >> 6);
        int b0 = m & 63;
        #pragma unroll
        for (int j = 0; j < 4; j++)
            wmma::store_matrix_sync(&g_pre[gate][t][b0][h0 + n0 + j * 16],
                                    acc[i][j], NH, wmma::mem_row_major);
    }
}

// ===================== persistent recurrence (manual mma, B in regs) =========
// 128 CTAs x 256 threads. CTA owns 4 h-cols x 4 gates (N=16). 8 warps =
// 4 m-tiles x 2 K-halves. B fragments live in registers across all 256 steps.
#define R_SW_LD 24                              /* halves */
#define R_SH_LD 520
#define R_SW_BYTES (512 * R_SW_LD * 2)          /* 24576 */
#define R_SH_BYTES (64 * R_SH_LD * 2)           /* 66560 */
#define R_SACC_OFF (R_SW_BYTES + R_SH_BYTES)    /* 91136 */
#define R_ACC_LD 20
#define REC_SMEM (R_SACC_OFF + 2 * 64 * R_ACC_LD * 4)  /* 101376 */
#define RCTAS 128

__global__ __launch_bounds__(256) void rec_kernel(const float* __restrict__ Wfh,
                                                  const float* __restrict__ Wih,
                                                  const float* __restrict__ Wgh,
                                                  const float* __restrict__ Woh,
                                                  const float* __restrict__ bfp,
                                                  const float* __restrict__ bip,
                                                  const float* __restrict__ bgp,
                                                  const float* __restrict__ bop) {
    extern __shared__ char smraw[];
    __half* sW   = (__half*)smraw;                   // [512][24], col = gate*4+c
    __half* sH   = (__half*)(smraw + R_SW_BYTES);    // [64][520]
    float*  sAcc = (float*)(smraw + R_SACC_OFF);     // [2][64][20]

    const int cta = blockIdx.x;
    const int tid = threadIdx.x;
    const int lane = tid & 31;
    const int colbase = cta * 4;
    int* const pcnt = &g_count;

    // Load W slice: 512 rows x 16 cols (n = gate*4 + c)
    {
        const float* Wp[4] = {Wfh, Wih, Wgh, Woh};
        #pragma unroll 8
        for (int e = 0; e < 32; e++) {
            int idx = e * 256 + tid;                 // 8192
            int row = idx >> 4, c = idx & 15;
            float v = Wp[c >> 2][row * NH + colbase + (c & 3)];
            sW[row * R_SW_LD + c] = __float2half_rn(v);
        }
    }
    __syncthreads();

    const int w     = tid >> 5;
    const int mwarp = (w & 3) * 16;                  // m-tile base row
    const int kh    = w >> 2;                        // K-half
    const int kbase = kh * 256;

    // --- B fragments to registers (once). m16n8k16 B layout:
    // b0 = {B[k0][n], B[k0+1][n]}, b1 = {B[k0+8][n], B[k0+9][n]},
    // k0 = step*16 + (lane%4)*2, n = nf*8 + lane/4.
    uint32_t Breg[16][2][2];
    {
        const int kq = (lane & 3) * 2;
        const int nb = lane >> 2;
        #pragma unroll
        for (int s = 0; s < 16; s++) {
            int k0 = kbase + s * 16 + kq;
            #pragma unroll
            for (int nf = 0; nf < 2; nf++) {
                int n = nf * 8 + nb;
                __half2 v0 = __halves2half2(sW[(k0 + 0) * R_SW_LD + n],
                                            sW[(k0 + 1) * R_SW_LD + n]);
                __half2 v1 = __halves2half2(sW[(k0 + 8) * R_SW_LD + n],
                                            sW[(k0 + 9) * R_SW_LD + n]);
                Breg[s][nf][0] = *reinterpret_cast<uint32_t*>(&v0);
                Breg[s][nf][1] = *reinterpret_cast<uint32_t*>(&v1);
            }
        }
    }

    const int b  = tid >> 2;                         // 0..63
    const int c  = tid & 3;                          // 0..3
    const float bfv = bfp[colbase + c];
    const float biv = bip[colbase + c];
    const float bgv = bgp[colbase + c];
    const float bov = bop[colbase + c];
    float c_reg = 0.f;

    const uint32_t sHa = smem_u32(sH);
    const uint32_t ldmAddrBase = sHa + ((mwarp + (lane & 15)) * R_SH_LD + kbase + (lane >> 4) * 8) * 2;

    for (int t = 0; t < NT; t++) {
        // hoist pre-activation loads above the barrier poll (latency hidden)
        const float pf = g_pre[0][t][b][colbase + c];
        const float pi = g_pre[1][t][b][colbase + c];
        const float pg_ = g_pre[2][t][b][colbase + c];
        const float po = g_pre[3][t][b][colbase + c];

        if (t > 0) {
            if (tid == 0) {
                int target = RCTAS * t, v;
                do {
                    asm volatile("ld.acquire.gpu.b32 %0, [%1];" : "=r"(v) : "l"(pcnt) : "memory");
                } while (v < target);
            }
            __syncthreads();
        }

        // stage h (fp16, 64KB) via cp.async: 4096 chunks -> 16/thread
        const __half* hin = g_hh[t & 1];
        #pragma unroll
        for (int e = 0; e < 16; e++) {
            int idx = e * 256 + tid;
            int row = idx >> 6, cc = idx & 63;
            CP_ASYNC_16(sHa + (row * R_SH_LD + cc * 8) * 2,
                        hin + row * NH + cc * 8);
        }
        CP_COMMIT();
        CP_WAIT_ALL();
        __syncthreads();

        // GEMM: [64x512] @ [512x16]; warp (mwarp, kh): 16 k16-steps.
        float acc[2][2][4];
        #pragma unroll
        for (int nf = 0; nf < 2; nf++)
            #pragma unroll
            for (int pq = 0; pq < 2; pq++)
                #pragma unroll
                for (int j = 0; j < 4; j++) acc[nf][pq][j] = 0.f;

        #pragma unroll
        for (int s = 0; s < 16; s++) {
            uint32_t a0, a1, a2, a3;
            LDMATRIX_X4(a0, a1, a2, a3, ldmAddrBase + s * 32);   // 16 halves in k
            MMA_16816(acc[0][s & 1], a0, a1, a2, a3, Breg[s][0][0], Breg[s][0][1]);
            MMA_16816(acc[1][s & 1], a0, a1, a2, a3, Breg[s][1][0], Breg[s][1][1]);
        }

        // store partials: c layout row = lane/4 (+8), col = (lane%4)*2 (+1)
        {
            int r0 = lane >> 2, cc0 = (lane & 3) * 2;
            #pragma unroll
            for (int nf = 0; nf < 2; nf++) {
                float2 v0 = make_float2(acc[nf][0][0] + acc[nf][1][0],
                                        acc[nf][0][1] + acc[nf][1][1]);
                float2 v1 = make_float2(acc[nf][0][2] + acc[nf][1][2],
                                        acc[nf][0][3] + acc[nf][1][3]);
                int n = nf * 8 + cc0;
                *reinterpret_cast<float2*>(sAcc + (kh * 64 + mwarp + r0) * R_ACC_LD + n) = v0;
                *reinterpret_cast<float2*>(sAcc + (kh * 64 + mwarp + r0 + 8) * R_ACC_LD + n) = v1;
            }
        }
        __syncthreads();

        // elementwise: thread handles (b, c) for all 4 gates
        const float* a0p = sAcc + b * R_ACC_LD;
        const float* a1p = sAcc + (64 + b) * R_ACC_LD;
        float af = a0p[0 * 4 + c] + a1p[0 * 4 + c];
        float ai = a0p[1 * 4 + c] + a1p[1 * 4 + c];
        float ag = a0p[2 * 4 + c] + a1p[2 * 4 + c];
        float ao = a0p[3 * 4 + c] + a1p[3 * 4 + c];

        float f = 1.f / (1.f + expf(-(pf + bfv + af)));
        float i = 1.f / (1.f + expf(-(pi + biv + ai)));
        float g = tanhf(pg_ + bgv + ag);
        float o = 1.f / (1.f + expf(-(po + bov + ao)));

        c_reg = f * c_reg + i * g;
        float hv = o * tanhf(c_reg);

        __half* hout = g_hh[(t + 1) & 1];
        __stcg(hout + b * NH + colbase + c, __float2half_rn(hv));
        if (t == NT - 1) g_h_final[b * NH + colbase + c] = hv;

        __syncthreads();
        if (tid == 0) {
            asm volatile("red.release.gpu.add.s32 [%0], %1;" :: "l"(pcnt), "r"(1) : "memory");
        }
    }

    g_c[b * NH + colbase + c] = c_reg;
}

// ===================== head =====================
__global__ __launch_bounds__(256) void final_kernel(const float* __restrict__ Wl,
                                                    const float* __restrict__ bl,
                                                    float* __restrict__ out,
                                                    int out_size) {
    const float* h = g_h_final;
    if (blockIdx.x == 0) {
        for (int idx = threadIdx.x; idx < NB * NO; idx += blockDim.x) {
            int b = idx / NO, o = idx % NO;
            float s = bl[o];
            #pragma unroll 8
            for (int k = 0; k < NH; k++) s += h[b * NH + k] * Wl[k * NO + o];
            if (idx < out_size) out[idx] = s;
        }
    }
    int gidx   = blockIdx.x * blockDim.x + threadIdx.x;
    int stride = gridDim.x * blockDim.x;
    for (int i = gidx; i < NB * NH; i += stride) {
        if (NB * NO + i < out_size)           out[NB * NO + i] = h[i];
        if (NB * NO + NB * NH + i < out_size) out[NB * NO + NB * NH + i] = g_c[i];
    }
}

// ===================== launch =====================
extern "C" void kernel_launch(void* const* d_in, const int* in_sizes, int n_in,
                              void* d_out, int out_size) {
    const int*   x   = (const int*)  d_in[0];
    const float* emb = (const float*)d_in[1];
    const float* Wfx = (const float*)d_in[2];
    const float* Wfh = (const float*)d_in[3];
    const float* bf  = (const float*)d_in[4];
    const float* Wix = (const float*)d_in[5];
    const float* Wih = (const float*)d_in[6];
    const float* bi  = (const float*)d_in[7];
    const float* Wgx = (const float*)d_in[8];
    const float* Wgh = (const float*)d_in[9];
    const float* bg  = (const float*)d_in[10];
    const float* Wox = (const float*)d_in[11];
    const float* Woh = (const float*)d_in[12];
    const float* bo  = (const float*)d_in[13];
    const float* Wl  = (const float*)d_in[14];
    const float* bl  = (const float*)d_in[15];
    float* out = (float*)d_out;

    cudaFuncSetAttribute(pre_kernel, cudaFuncAttributeMaxDynamicSharedMemorySize, PRE_SMEM);
    cudaFuncSetAttribute(rec_kernel, cudaFuncAttributeMaxDynamicSharedMemorySize, REC_SMEM);

    convert_emb<<<2048, 256>>>(emb);
    convert_wx<<<dim3(1024, 4), 256>>>(Wfx, Wix, Wgx, Wox);
    init_state<<<(NB * NH + 255) / 256, 256>>>();

    pre_kernel<<<dim3(8, 128), 256, PRE_SMEM>>>(x);

    rec_kernel<<<RCTAS, 256, REC_SMEM>>>(Wfh, Wih, Wgh, Woh, bf, bi, bg, bo);

    final_kernel<<<132, 256>>>(Wl, bl, out, out_size);
}

// round 10
// speedup vs baseline: 9.9429x; 1.0449x over previous
#include <cuda_runtime.h>
#include <mma.h>
#include <cuda_fp16.h>
#include <cstdint>

using namespace nvcuda;

#define NB 64
#define NP 16
#define NT 256
#define NI 256
#define NH 512
#define NO 5
#define NK (NP*NI)   /* 4096 */
#define NV 50000

// Scratch (device globals per harness rules)
__device__ float  g_pre[4][NT][NB][NH];   // [gate][t][b][h]
__device__ __half g_embH[NV * NI];        // fp16 embedding table
__device__ __half g_WcH[4][NK][NH];       // fp16 x-weights (natural layout)
__device__ __half g_hh[2][NB*NH];         // fp16 hidden state ping-pong
__device__ float  g_h_final[NB*NH];
__device__ int    g_count;

__device__ __forceinline__ uint32_t smem_u32(const void* p) {
    uint32_t a;
    asm("{ .reg .u64 t; cvta.to.shared.u64 t, %1; cvt.u32.u64 %0, t; }" : "=r"(a) : "l"(p));
    return a;
}
#define CP_ASYNC_16(dst, src) \
    asm volatile("cp.async.cg.shared.global [%0], [%1], 16;" :: "r"(dst), "l"(src))
#define CP_ASYNC_16_PRED(dst, src, nbytes) \
    asm volatile("cp.async.cg.shared.global [%0], [%1], 16, %2;" :: "r"(dst), "l"(src), "r"(nbytes))
#define CP_COMMIT() asm volatile("cp.async.commit_group;" ::: "memory")
#define CP_WAIT(n)  asm volatile("cp.async.wait_group %0;" :: "n"(n) : "memory")
#define CP_WAIT_ALL() asm volatile("cp.async.wait_all;" ::: "memory")

#define LDMATRIX_X4(a0, a1, a2, a3, addr) \
    asm volatile("ldmatrix.sync.aligned.m8n8.x4.shared.b16 {%0,%1,%2,%3}, [%4];" \
                 : "=r"(a0), "=r"(a1), "=r"(a2), "=r"(a3) : "r"(addr))

#define MMA_16816(d, a0, a1, a2, a3, b0, b1) \
    asm volatile("mma.sync.aligned.m16n8k16.row.col.f32.f16.f16.f32 " \
                 "{%0,%1,%2,%3}, {%4,%5,%6,%7}, {%8,%9}, {%0,%1,%2,%3};" \
                 : "+f"((d)[0]), "+f"((d)[1]), "+f"((d)[2]), "+f"((d)[3]) \
                 : "r"(a0), "r"(a1), "r"(a2), "r"(a3), "r"(b0), "r"(b1))

// ===================== prep: fp32 -> fp16 =====================
__global__ __launch_bounds__(256) void convert_emb(const float* __restrict__ emb) {
    long idx = (long)blockIdx.x * blockDim.x + threadIdx.x;
    long n = (long)NV * NI;
    for (; idx < n; idx += (long)gridDim.x * blockDim.x)
        g_embH[idx] = __float2half_rn(emb[idx]);
}
__global__ __launch_bounds__(256) void convert_wx(const float* __restrict__ w0,
                                                  const float* __restrict__ w1,
                                                  const float* __restrict__ w2,
                                                  const float* __restrict__ w3) {
    const float* W = (blockIdx.y == 0) ? w0 : (blockIdx.y == 1) ? w1 : (blockIdx.y == 2) ? w2 : w3;
    long idx = (long)blockIdx.x * blockDim.x + threadIdx.x;
    long n = (long)NK * NH;
    for (; idx < n; idx += (long)gridDim.x * blockDim.x)
        g_WcH[blockIdx.y][0][idx] = __float2half_rn(W[idx]);
}

__global__ __launch_bounds__(256) void init_state() {
    int idx = blockIdx.x * blockDim.x + threadIdx.x;
    if (idx < NB * NH) { g_hh[0][idx] = __ushort_as_half((unsigned short)0); }
    if (idx == 0) g_count = 0;
}

// ===================== pre-activation GEMM (fp16 WMMA) =====================
// CTA: M=128 (2 t x 64 b) x N=256, K=4096 in 64 slabs of 64. 3-stage cp.async,
// single __syncthreads per slab. 8 warps, warp tile 64x64.
#define A_LDH 72                              /* halves */
#define B_LDH 264
#define A_BYTES (128 * A_LDH * 2)             /* 18432 */
#define B_BYTES (64 * B_LDH * 2)              /* 33792 */
#define STAGE_BYTES (A_BYTES + B_BYTES)       /* 52224 */
#define TOK_BYTES 8192
#define PRE_SMEM (TOK_BYTES + 3 * STAGE_BYTES)    /* 164864 */

__global__ __launch_bounds__(256) void pre_kernel(const int* __restrict__ x) {
    extern __shared__ char smem[];
    int* sTok = (int*)smem;
    const uint32_t stage0 = smem_u32(smem + TOK_BYTES);

    const int tid  = threadIdx.x;
    const int gate = blockIdx.x >> 1;
    const int h0   = (blockIdx.x & 1) * 256;
    const int t0   = blockIdx.y * 2;

    #pragma unroll
    for (int e = 0; e < 8; e++) {
        int idx = e * 256 + tid;
        int tt = idx >> 10, rem = idx & 1023;
        int p = rem >> 6, b = rem & 63;
        sTok[idx] = x[b * (NP * NT) + p * NT + (t0 + tt)];
    }
    __syncthreads();

    const __half* Wbase = &g_WcH[gate][0][h0];

    auto issue_slab = [&](int s, int st) {
        const uint32_t aB = stage0 + st * STAGE_BYTES;
        const uint32_t bB = aB + A_BYTES;
        const int p  = s >> 2;
        const int i0 = (s & 3) * 64;
        #pragma unroll
        for (int e = 0; e < 4; e++) {
            int idx = e * 256 + tid;
            int row = idx >> 3, c8 = idx & 7;
            int tok = sTok[(row >> 6) * 1024 + p * 64 + (row & 63)];
            const __half* src = g_embH + (long)tok * NI + i0 + c8 * 8;
            CP_ASYNC_16_PRED(aB + (row * A_LDH + c8 * 8) * 2, src, tok ? 16 : 0);
        }
        const int k0 = s * 64;
        #pragma unroll
        for (int e = 0; e < 8; e++) {
            int idx = e * 256 + tid;
            int row = idx >> 5, c8 = idx & 31;
            const __half* src = Wbase + (long)(k0 + row) * NH + c8 * 8;
            CP_ASYNC_16(bB + (row * B_LDH + c8 * 8) * 2, src);
        }
        CP_COMMIT();
    };

    const int w  = tid >> 5;
    const int m0 = (w & 1) * 64;
    const int n0 = (w >> 1) * 64;

    wmma::fragment<wmma::accumulator, 16, 16, 16, float> acc[4][4];
    #pragma unroll
    for (int i = 0; i < 4; i++)
        #pragma unroll
        for (int j = 0; j < 4; j++) wmma::fill_fragment(acc[i][j], 0.f);

    issue_slab(0, 0);
    issue_slab(1, 1);

    for (int s = 0; s < 64; s++) {
        CP_WAIT(1);
        __syncthreads();
        if (s + 2 < 64) issue_slab(s + 2, (s + 2) % 3);
        else CP_COMMIT();

        const char* base = smem + TOK_BYTES + (s % 3) * STAGE_BYTES;
        const __half* bA = (const __half*)base;
        const __half* bB = (const __half*)(base + A_BYTES);

        #pragma unroll
        for (int kk = 0; kk < 4; kk++) {
            wmma::fragment<wmma::matrix_a, 16, 16, 16, __half, wmma::row_major> fa[4];
            wmma::fragment<wmma::matrix_b, 16, 16, 16, __half, wmma::row_major> fb[4];
            #pragma unroll
            for (int i = 0; i < 4; i++)
                wmma::load_matrix_sync(fa[i], bA + (m0 + i * 16) * A_LDH + kk * 16, A_LDH);
            #pragma unroll
            for (int j = 0; j < 4; j++)
                wmma::load_matrix_sync(fb[j], bB + (kk * 16) * B_LDH + n0 + j * 16, B_LDH);
            #pragma unroll
            for (int i = 0; i < 4; i++)
                #pragma unroll
                for (int j = 0; j < 4; j++)
                    wmma::mma_sync(acc[i][j], fa[i], fb[j], acc[i][j]);
        }
    }

    #pragma unroll
    for (int i = 0; i < 4; i++) {
        int m = m0 + i * 16;
        int t = t0 + (m >> 6);
        int b0 = m & 63;
        #pragma unroll
        for (int j = 0; j < 4; j++)
            wmma::store_matrix_sync(&g_pre[gate][t][b0][h0 + n0 + j * 16],
                                    acc[i][j], NH, wmma::mem_row_major);
    }
}

// ===================== persistent recurrence (warp-private staging) ==========
// 128 CTAs x 256 threads. CTA owns 4 h-cols x 4 gates (N=16). 8 warps =
// 4 m-tiles x 2 K-halves. Each warp stages ONLY its own 16-row x 256-col h
// slice (8KB) and proceeds to mma without any CTA-wide sync. B in registers.
// Head (out = h@W_lin + b_lin) computed by CTA 0 after a final barrier; all
// CTAs write their h_t / c_t slices directly to d_out.
#define R_SW_LD 24                              /* halves */
#define R_SH_LD 520
#define R_SW_BYTES (512 * R_SW_LD * 2)          /* 24576 */
#define R_SH_BYTES (64 * R_SH_LD * 2)           /* 66560 */
#define R_SACC_OFF (R_SW_BYTES + R_SH_BYTES)    /* 91136 */
#define R_ACC_LD 20
#define R_WL_OFF (R_SACC_OFF + 2 * 64 * R_ACC_LD * 4)   /* 101376 */
#define REC_SMEM (R_WL_OFF + 512 * NO * 4)              /* 111616 */
#define RCTAS 128

__global__ __launch_bounds__(256) void rec_kernel(const float* __restrict__ Wfh,
                                                  const float* __restrict__ Wih,
                                                  const float* __restrict__ Wgh,
                                                  const float* __restrict__ Woh,
                                                  const float* __restrict__ bfp,
                                                  const float* __restrict__ bip,
                                                  const float* __restrict__ bgp,
                                                  const float* __restrict__ bop,
                                                  const float* __restrict__ Wl,
                                                  const float* __restrict__ bl,
                                                  float* __restrict__ out,
                                                  int out_size) {
    extern __shared__ char smraw[];
    __half* sW   = (__half*)smraw;                   // [512][24], col = gate*4+c
    __half* sH   = (__half*)(smraw + R_SW_BYTES);    // [64][520]
    float*  sAcc = (float*)(smraw + R_SACC_OFF);     // [2][64][20]

    const int cta = blockIdx.x;
    const int tid = threadIdx.x;
    const int lane = tid & 31;
    const int colbase = cta * 4;
    int* const pcnt = &g_count;

    // Load W slice: 512 rows x 16 cols (n = gate*4 + c)
    {
        const float* Wp[4] = {Wfh, Wih, Wgh, Woh};
        #pragma unroll 8
        for (int e = 0; e < 32; e++) {
            int idx = e * 256 + tid;                 // 8192
            int row = idx >> 4, c = idx & 15;
            float v = Wp[c >> 2][row * NH + colbase + (c & 3)];
            sW[row * R_SW_LD + c] = __float2half_rn(v);
        }
    }
    __syncthreads();

    const int w     = tid >> 5;
    const int mwarp = (w & 3) * 16;                  // m-tile base row
    const int kh    = w >> 2;                        // K-half
    const int kbase = kh * 256;

    // B fragments to registers (once)
    uint32_t Breg[16][2][2];
    {
        const int kq = (lane & 3) * 2;
        const int nb = lane >> 2;
        #pragma unroll
        for (int s = 0; s < 16; s++) {
            int k0 = kbase + s * 16 + kq;
            #pragma unroll
            for (int nf = 0; nf < 2; nf++) {
                int n = nf * 8 + nb;
                __half2 v0 = __halves2half2(sW[(k0 + 0) * R_SW_LD + n],
                                            sW[(k0 + 1) * R_SW_LD + n]);
                __half2 v1 = __halves2half2(sW[(k0 + 8) * R_SW_LD + n],
                                            sW[(k0 + 9) * R_SW_LD + n]);
                Breg[s][nf][0] = *reinterpret_cast<uint32_t*>(&v0);
                Breg[s][nf][1] = *reinterpret_cast<uint32_t*>(&v1);
            }
        }
    }

    const int b  = tid >> 2;                         // 0..63
    const int c  = tid & 3;                          // 0..3
    const float bfv = bfp[colbase + c];
    const float biv = bip[colbase + c];
    const float bgv = bgp[colbase + c];
    const float bov = bop[colbase + c];
    float c_reg = 0.f;

    const uint32_t sHa = smem_u32(sH);
    // warp-private staging: 16 rows x 256 cols; chunk (ch,lane): row=mwarp+ch, col=lane*8
    const uint32_t stageDst = sHa + (kbase + lane * 8) * 2;
    // ldmatrix base for this warp's A tile
    const uint32_t ldmAddrBase = sHa + ((mwarp + (lane & 15)) * R_SH_LD + kbase + (lane >> 4) * 8) * 2;

    for (int t = 0; t < NT; t++) {
        // hoist pre-activation loads above the barrier poll
        const float pf  = g_pre[0][t][b][colbase + c];
        const float pi  = g_pre[1][t][b][colbase + c];
        const float pg_ = g_pre[2][t][b][colbase + c];
        const float po  = g_pre[3][t][b][colbase + c];

        if (t > 0) {
            if (tid == 0) {
                int target = RCTAS * t, v;
                do {
                    asm volatile("ld.acquire.gpu.b32 %0, [%1];" : "=r"(v) : "l"(pcnt) : "memory");
                } while (v < target);
            }
            __syncthreads();
        }

        // warp-private h staging: 16 chunks of 16B per lane (own rows, own K-half)
        const __half* hin = g_hh[t & 1] + kbase + lane * 8;
        #pragma unroll
        for (int ch = 0; ch < 16; ch++) {
            CP_ASYNC_16(stageDst + (mwarp + ch) * (R_SH_LD * 2),
                        hin + (mwarp + ch) * NH);
        }
        CP_COMMIT();
        CP_WAIT_ALL();
        __syncwarp();

        // GEMM on own slice: 16 k16-steps
        float acc[2][2][4];
        #pragma unroll
        for (int nf = 0; nf < 2; nf++)
            #pragma unroll
            for (int pq = 0; pq < 2; pq++)
                #pragma unroll
                for (int j = 0; j < 4; j++) acc[nf][pq][j] = 0.f;

        #pragma unroll
        for (int s = 0; s < 16; s++) {
            uint32_t a0, a1, a2, a3;
            LDMATRIX_X4(a0, a1, a2, a3, ldmAddrBase + s * 32);
            MMA_16816(acc[0][s & 1], a0, a1, a2, a3, Breg[s][0][0], Breg[s][0][1]);
            MMA_16816(acc[1][s & 1], a0, a1, a2, a3, Breg[s][1][0], Breg[s][1][1]);
        }

        // store partials
        {
            int r0 = lane >> 2, cc0 = (lane & 3) * 2;
            #pragma unroll
            for (int nf = 0; nf < 2; nf++) {
                float2 v0 = make_float2(acc[nf][0][0] + acc[nf][1][0],
                                        acc[nf][0][1] + acc[nf][1][1]);
                float2 v1 = make_float2(acc[nf][0][2] + acc[nf][1][2],
                                        acc[nf][0][3] + acc[nf][1][3]);
                int n = nf * 8 + cc0;
                *reinterpret_cast<float2*>(sAcc + (kh * 64 + mwarp + r0) * R_ACC_LD + n) = v0;
                *reinterpret_cast<float2*>(sAcc + (kh * 64 + mwarp + r0 + 8) * R_ACC_LD + n) = v1;
            }
        }
        __syncthreads();

        // elementwise: thread handles (b, c) for all 4 gates
        const float* a0p = sAcc + b * R_ACC_LD;
        const float* a1p = sAcc + (64 + b) * R_ACC_LD;
        float af = a0p[0 * 4 + c] + a1p[0 * 4 + c];
        float ai = a0p[1 * 4 + c] + a1p[1 * 4 + c];
        float ag = a0p[2 * 4 + c] + a1p[2 * 4 + c];
        float ao = a0p[3 * 4 + c] + a1p[3 * 4 + c];

        float f = 1.f / (1.f + expf(-(pf + bfv + af)));
        float i = 1.f / (1.f + expf(-(pi + biv + ai)));
        float g = tanhf(pg_ + bgv + ag);
        float o = 1.f / (1.f + expf(-(po + bov + ao)));

        c_reg = f * c_reg + i * g;
        float hv = o * tanhf(c_reg);

        __half* hout = g_hh[(t + 1) & 1];
        __stcg(hout + b * NH + colbase + c, __float2half_rn(hv));
        if (t == NT - 1) {
            g_h_final[b * NH + colbase + c] = hv;
            int hidx = NB * NO + b * NH + colbase + c;
            int cidx = NB * NO + NB * NH + b * NH + colbase + c;
            if (hidx < out_size) out[hidx] = hv;
            if (cidx < out_size) out[cidx] = c_reg;
        }

        __syncthreads();
        if (tid == 0) {
            asm volatile("red.release.gpu.add.s32 [%0], %1;" :: "l"(pcnt), "r"(1) : "memory");
        }
    }

    // ---- head: CTA 0 computes out = h_final @ W_lin + b_lin ----
    if (cta == 0) {
        float* sWl = (float*)(smraw + R_WL_OFF);     // [512][5]
        for (int idx = tid; idx < NH * NO; idx += 256)
            sWl[idx] = Wl[idx];
        if (tid == 0) {
            int target = RCTAS * NT, v;
            do {
                asm volatile("ld.acquire.gpu.b32 %0, [%1];" : "=r"(v) : "l"(pcnt) : "memory");
            } while (v < target);
        }
        __syncthreads();
        for (int idx = tid; idx < NB * NO; idx += 256) {
            int bb = idx / NO, o = idx % NO;
            float s = bl[o];
            #pragma unroll 8
            for (int k = 0; k < NH; k++) s += g_h_final[bb * NH + k] * sWl[k * NO + o];
            if (idx < out_size) out[idx] = s;
        }
    }
}

// ===================== launch =====================
extern "C" void kernel_launch(void* const* d_in, const int* in_sizes, int n_in,
                              void* d_out, int out_size) {
    const int*   x   = (const int*)  d_in[0];
    const float* emb = (const float*)d_in[1];
    const float* Wfx = (const float*)d_in[2];
    const float* Wfh = (const float*)d_in[3];
    const float* bf  = (const float*)d_in[4];
    const float* Wix = (const float*)d_in[5];
    const float* Wih = (const float*)d_in[6];
    const float* bi  = (const float*)d_in[7];
    const float* Wgx = (const float*)d_in[8];
    const float* Wgh = (const float*)d_in[9];
    const float* bg  = (const float*)d_in[10];
    const float* Wox = (const float*)d_in[11];
    const float* Woh = (const float*)d_in[12];
    const float* bo  = (const float*)d_in[13];
    const float* Wl  = (const float*)d_in[14];
    const float* bl  = (const float*)d_in[15];
    float* out = (float*)d_out;

    cudaFuncSetAttribute(pre_kernel, cudaFuncAttributeMaxDynamicSharedMemorySize, PRE_SMEM);
    cudaFuncSetAttribute(rec_kernel, cudaFuncAttributeMaxDynamicSharedMemorySize, REC_SMEM);

    convert_emb<<<2048, 256>>>(emb);
    convert_wx<<<dim3(1024, 4), 256>>>(Wfx, Wix, Wgx, Wox);
    init_state<<<(NB * NH + 255) / 256, 256>>>();

    pre_kernel<<<dim3(8, 128), 256, PRE_SMEM>>>(x);

    rec_kernel<<<RCTAS, 256, REC_SMEM>>>(Wfh, Wih, Wgh, Woh, bf, bi, bg, bo,
                                         Wl, bl, out, out_size);
}